// round 10
// baseline (speedup 1.0000x reference)
#include <cuda_runtime.h>
#include <cuda_fp16.h>

#define BB 32
#define LL 1024
#define HH 1280
#define PP 128
#define NROWS (BB * LL)

// ---------------------------------------------------------------------------
// Helpers
// ---------------------------------------------------------------------------
__device__ __forceinline__ unsigned smem_to_u32(const void* p) {
    unsigned a;
    asm("{ .reg .u64 t; cvta.to.shared.u64 t, %1; cvt.u32.u64 %0, t; }" : "=r"(a) : "l"(p));
    return a;
}
static __device__ __forceinline__ unsigned sw128(unsigned off) {
    return off ^ ((off >> 3) & 0x70);
}
__device__ __forceinline__ unsigned f16pack(float lo, float hi) {
    unsigned r;
    asm("cvt.rn.f16x2.f32 %0, %1, %2;" : "=r"(r) : "f"(hi), "f"(lo));
    return r;
}

#define LDSM4(r0, r1, r2, r3, addr)                                          \
    asm volatile("ldmatrix.sync.aligned.m8n8.x4.shared.b16 {%0,%1,%2,%3}, [%4];" \
                 : "=r"(r0), "=r"(r1), "=r"(r2), "=r"(r3) : "r"(addr))

#define MMA(d, a, b)                                                         \
    asm volatile("mma.sync.aligned.m16n8k16.row.col.f32.f16.f16.f32 "        \
                 "{%0,%1,%2,%3},{%4,%5,%6,%7},{%8,%9},{%0,%1,%2,%3};"        \
                 : "+f"((d)[0]), "+f"((d)[1]), "+f"((d)[2]), "+f"((d)[3])    \
                 : "r"((a)[0]), "r"((a)[1]), "r"((a)[2]), "r"((a)[3]),       \
                   "r"((b)[0]), "r"((b)[1]))

#define CP16(dst, src) \
    asm volatile("cp.async.cg.shared.global [%0], [%1], 16;" :: "r"(dst), "l"(src))
#define CP_COMMIT() asm volatile("cp.async.commit_group;" ::: "memory")
#define CP_WAIT0()  asm volatile("cp.async.wait_group 0;" ::: "memory")

// ---------------------------------------------------------------------------
// Device scratch
// ---------------------------------------------------------------------------
__device__ __align__(16) __half g_emb[NROWS * PP];
__device__ __align__(16) __half g_wt[PP * HH];   // [n][k] K-major
__device__ float g_partial[BB * 16];
__device__ int2 g_counts[BB];

// ---------------------------------------------------------------------------
// Kernel 0: W -> fp16, transposed to [n][k]
// ---------------------------------------------------------------------------
__global__ void kern_wt(const float* __restrict__ W) {
    int i = blockIdx.x * 256 + threadIdx.x;
    if (i >= HH * PP) return;
    int k = i / PP, n = i % PP;
    g_wt[n * HH + k] = __float2half_rn(W[i]);
}

__global__ void kern_nop() {}

// ---------------------------------------------------------------------------
// Kernel 1: proj + L2-normalize. M=64 rows/CTA (512 CTAs), occ 4 single wave,
// double-buffered A (fp16, converted in regs) and B, ONE sync per k-chunk.
// smem: bias @0, ssbuf @512 (1KB), A bufs @2048 (2x8KB), B bufs @18432 (2x16KB)
// ---------------------------------------------------------------------------
#define P_A(b) (2048 + (b) * 8192)
#define P_B(b) (18432 + (b) * 16384)
#define PROJ_SMEM 51200

__global__ __launch_bounds__(256, 4)
void kern_proj(const float* __restrict__ hid, const float* __restrict__ bias) {
    extern __shared__ char sm[];
    const unsigned sb = smem_to_u32(sm);
    const int tid = threadIdx.x, lane = tid & 31, wid = tid >> 5;
    const int wm = wid & 1, wn = wid >> 1;
    const int m0 = wm * 32, n0 = wn * 32;
    const int row0 = blockIdx.x * 64;
    float* bias_s = (float*)sm;
    float* ssbuf = (float*)(sm + 512);

    if (tid < 128) bias_s[tid] = bias[tid];

    float acc[2][4][4];
#pragma unroll
    for (int mt = 0; mt < 2; mt++)
#pragma unroll
        for (int nt = 0; nt < 4; nt++)
#pragma unroll
            for (int e = 0; e < 4; e++) acc[mt][nt][e] = 0.f;

    // ---- prologue: B0 cp.async; A0 LDG+convert+store ----
#pragma unroll
    for (int i = 0; i < 4; i++) {
        int u = i * 256 + tid;
        int n = u >> 3, k8 = u & 7;
        CP16(sb + P_B(0) + sw128((unsigned)(n * 128 + k8 * 16)),
             g_wt + (size_t)n * HH + k8 * 8);
    }
    CP_COMMIT();
    {
#pragma unroll
        for (int q = 0; q < 2; q++) {
            int u = q * 256 + tid;
            int row = u >> 3, k8 = u & 7;
            const float* s = hid + (size_t)(row0 + row) * HH + k8 * 8;
            float4 v0 = *(const float4*)s;
            float4 v1 = *(const float4*)(s + 4);
            uint4 ra = make_uint4(f16pack(v0.x, v0.y), f16pack(v0.z, v0.w),
                                  f16pack(v1.x, v1.y), f16pack(v1.z, v1.w));
            *(uint4*)(sm + P_A(0) + sw128((unsigned)(row * 128 + k8 * 16))) = ra;
        }
    }
    CP_WAIT0();
    __syncthreads();

#pragma unroll 1
    for (int c = 0; c < 20; c++) {
        const int buf = c & 1;
        // issue next chunk's loads up front (hidden under the mainloop)
        float4 v00, v01, v10, v11;
        if (c < 19) {
            const int k0n = (c + 1) * 64;
            {
                int u = tid;
                int row = u >> 3, k8 = u & 7;
                const float* s = hid + (size_t)(row0 + row) * HH + k0n + k8 * 8;
                v00 = *(const float4*)s;
                v01 = *(const float4*)(s + 4);
            }
            {
                int u = 256 + tid;
                int row = u >> 3, k8 = u & 7;
                const float* s = hid + (size_t)(row0 + row) * HH + k0n + k8 * 8;
                v10 = *(const float4*)s;
                v11 = *(const float4*)(s + 4);
            }
#pragma unroll
            for (int i = 0; i < 4; i++) {
                int u = i * 256 + tid;
                int n = u >> 3, k8 = u & 7;
                CP16(sb + P_B(buf ^ 1) + sw128((unsigned)(n * 128 + k8 * 16)),
                     g_wt + (size_t)n * HH + k0n + k8 * 8);
            }
            CP_COMMIT();
        }

        // mainloop on buf
        const unsigned a_base = sb + P_A(buf);
        const unsigned b_base = sb + P_B(buf);
#pragma unroll
        for (int kk = 0; kk < 4; kk++) {
            unsigned ah[2][4], bh[4][2];
#pragma unroll
            for (int mt = 0; mt < 2; mt++) {
                unsigned r = m0 + mt * 16 + (lane & 15);
                unsigned off = sw128(r * 128 + kk * 32 + ((lane >> 4) << 4));
                LDSM4(ah[mt][0], ah[mt][1], ah[mt][2], ah[mt][3], a_base + off);
            }
#pragma unroll
            for (int p = 0; p < 2; p++) {
                unsigned q = lane >> 3;
                unsigned nr = n0 + p * 16 + ((q >> 1) << 3) + (lane & 7);
                unsigned off = sw128(nr * 128 + kk * 32 + ((q & 1) << 4));
                unsigned t0, t1, t2, t3;
                LDSM4(t0, t1, t2, t3, b_base + off);
                bh[2 * p][0] = t0; bh[2 * p][1] = t1;
                bh[2 * p + 1][0] = t2; bh[2 * p + 1][1] = t3;
            }
#pragma unroll
            for (int mt = 0; mt < 2; mt++)
#pragma unroll
                for (int nt = 0; nt < 4; nt++)
                    MMA(acc[mt][nt], ah[mt], bh[nt]);
        }

        // convert + store next A into buf^1 (safe: laggards read buf only)
        if (c < 19) {
            {
                int u = tid;
                int row = u >> 3, k8 = u & 7;
                uint4 ra = make_uint4(f16pack(v00.x, v00.y), f16pack(v00.z, v00.w),
                                      f16pack(v01.x, v01.y), f16pack(v01.z, v01.w));
                *(uint4*)(sm + P_A(buf ^ 1) + sw128((unsigned)(row * 128 + k8 * 16))) = ra;
            }
            {
                int u = 256 + tid;
                int row = u >> 3, k8 = u & 7;
                uint4 ra = make_uint4(f16pack(v10.x, v10.y), f16pack(v10.z, v10.w),
                                      f16pack(v11.x, v11.y), f16pack(v11.z, v11.w));
                *(uint4*)(sm + P_A(buf ^ 1) + sw128((unsigned)(row * 128 + k8 * 16))) = ra;
            }
            CP_WAIT0();
        }
        __syncthreads();
    }

    // ---- epilogue: bias, L2 norm, store fp16 emb ----
    float ss[4] = {0.f, 0.f, 0.f, 0.f};
#pragma unroll
    for (int mt = 0; mt < 2; mt++)
#pragma unroll
        for (int nt = 0; nt < 4; nt++)
#pragma unroll
            for (int e = 0; e < 4; e++) {
                int s = e >> 1;
                int col = n0 + nt * 8 + (lane & 3) * 2 + (e & 1);
                float v = acc[mt][nt][e] + bias_s[col];
                acc[mt][nt][e] = v;
                ss[mt * 2 + s] += v * v;
            }
#pragma unroll
    for (int r2 = 0; r2 < 4; r2++) {
        ss[r2] += __shfl_xor_sync(0xffffffffu, ss[r2], 1);
        ss[r2] += __shfl_xor_sync(0xffffffffu, ss[r2], 2);
    }
    if ((lane & 3) == 0) {
#pragma unroll
        for (int r2 = 0; r2 < 4; r2++) {
            int rowg = wm * 32 + (r2 >> 1) * 16 + (lane >> 2) + (r2 & 1) * 8;
            ssbuf[wn * 64 + rowg] = ss[r2];
        }
    }
    __syncthreads();
#pragma unroll
    for (int r2 = 0; r2 < 4; r2++) {
        int mt = r2 >> 1, s = r2 & 1;
        int rowg = wm * 32 + mt * 16 + (lane >> 2) + s * 8;
        float tot = ssbuf[rowg] + ssbuf[64 + rowg] + ssbuf[128 + rowg] + ssbuf[192 + rowg];
        float inv = rsqrtf(tot);
        inv = inv * (1.5f - 0.5f * tot * inv * inv);
        __half* oh = g_emb + (size_t)(row0 + rowg) * PP;
#pragma unroll
        for (int nt = 0; nt < 4; nt++) {
            int col = n0 + nt * 8 + (lane & 3) * 2;
            *(unsigned*)(oh + col) =
                f16pack(acc[mt][nt][s * 2] * inv, acc[mt][nt][s * 2 + 1] * inv);
        }
    }
}

// ---------------------------------------------------------------------------
// Kernel 2: fused sim-HMMA + contrastive stats — UNCHANGED from R9 (passing)
// ---------------------------------------------------------------------------
#define SM2_WPART 0
#define SM2_MASK  64
#define SM2_CNT   160
#define SM2_RED   256
#define SM2_A     5120
#define SM2_B     21504
#define SIM_SMEM  54272

__global__ __launch_bounds__(256, 4)
void kern_sim(const int* __restrict__ amask, const int* __restrict__ labels) {
    extern __shared__ char sm[];
    const unsigned sb = smem_to_u32(sm);
    const int tid = threadIdx.x, lane = tid & 31, wid = tid >> 5;
    const int wm = wid & 1, wn = wid >> 1;
    const int m0 = wm * 32, n0 = wn * 32;
    const int b = blockIdx.x >> 4, it = blockIdx.x & 15;
    const int i0 = it * 64;
    const __half* eb = g_emb + (size_t)b * LL * PP;
    float* wpart = (float*)(sm + SM2_WPART);
    unsigned* valm = (unsigned*)(sm + SM2_MASK);
    unsigned* posm = valm + 4;
    int* cnt = (int*)(sm + SM2_CNT);

#pragma unroll
    for (int i = 0; i < 4; i++) {
        int u = i * 256 + tid;
        int row = u >> 4, k8 = u & 15;
        unsigned off = (unsigned)((k8 >> 3) * 8192) +
                       sw128((unsigned)(row * 128 + (k8 & 7) * 16));
        CP16(sb + SM2_A + off, eb + (size_t)(i0 + row) * PP + k8 * 8);
    }
#pragma unroll
    for (int i = 0; i < 8; i++) {
        int u = i * 256 + tid;
        int row = u >> 4, k8 = u & 15;
        unsigned off = (unsigned)((k8 >> 3) * 16384) +
                       sw128((unsigned)(row * 128 + (k8 & 7) * 16));
        CP16(sb + SM2_B + off, eb + (size_t)row * PP + k8 * 8);
    }
    CP_COMMIT();

    int labi_[4], np_[4];
    float se_[4], sp_[4];
#pragma unroll
    for (int r2 = 0; r2 < 4; r2++) {
        int rowg = wm * 32 + (r2 >> 1) * 16 + (lane >> 2) + (r2 & 1) * 8;
        int gi = i0 + rowg;
        int lb = labels[b * LL + gi];
        labi_[r2] = ((amask[b * LL + gi] != 0) && (lb != -100)) ? lb : -1;
        se_[r2] = 0.f; sp_[r2] = 0.f; np_[r2] = 0;
    }
    const float invT = 1.0f / 0.07f;

#pragma unroll 1
    for (int jt = 0; jt < 8; jt++) {
        const int j0 = jt * 128;
        if (tid < 128) {
            int mm = amask[b * LL + j0 + tid];
            int lb = labels[b * LL + j0 + tid];
            int vv = (mm != 0) && (lb != -100);
            unsigned vmb = __ballot_sync(0xffffffffu, vv);
            if (lane == 0) valm[wid] = vmb;
#pragma unroll
            for (int l = 0; l < 4; l++) {
                unsigned pb = __ballot_sync(0xffffffffu, vv && (lb == l));
                if (lane == 0) posm[l * 4 + wid] = pb;
            }
        }
        CP_WAIT0();
        __syncthreads();

        float acc[2][4][4];
#pragma unroll
        for (int mt = 0; mt < 2; mt++)
#pragma unroll
            for (int nt = 0; nt < 4; nt++)
#pragma unroll
                for (int e = 0; e < 4; e++) acc[mt][nt][e] = 0.f;

#pragma unroll
        for (int kk = 0; kk < 8; kk++) {
            const unsigned chA = (unsigned)((kk >> 2) * 8192);
            const unsigned chB = (unsigned)((kk >> 2) * 16384);
            const unsigned kk2 = (kk & 3) * 32;
            unsigned ah[2][4], bh[4][2];
#pragma unroll
            for (int mt = 0; mt < 2; mt++) {
                unsigned r = m0 + mt * 16 + (lane & 15);
                unsigned off = chA + sw128(r * 128 + kk2 + ((lane >> 4) << 4));
                LDSM4(ah[mt][0], ah[mt][1], ah[mt][2], ah[mt][3], sb + SM2_A + off);
            }
#pragma unroll
            for (int p = 0; p < 2; p++) {
                unsigned q = lane >> 3;
                unsigned nr = n0 + p * 16 + ((q >> 1) << 3) + (lane & 7);
                unsigned off = chB + sw128(nr * 128 + kk2 + ((q & 1) << 4));
                unsigned t0, t1, t2, t3;
                LDSM4(t0, t1, t2, t3, sb + SM2_B + off);
                bh[2 * p][0] = t0; bh[2 * p][1] = t1;
                bh[2 * p + 1][0] = t2; bh[2 * p + 1][1] = t3;
            }
#pragma unroll
            for (int mt = 0; mt < 2; mt++)
#pragma unroll
                for (int nt = 0; nt < 4; nt++)
                    MMA(acc[mt][nt], ah[mt], bh[nt]);
        }

        const unsigned vmw = valm[wn];
        const int dt = (jt == (it >> 1));
        const int sh = (lane & 3) * 2;
#pragma unroll
        for (int r2 = 0; r2 < 4; r2++) {
            int mt = r2 >> 1, s = r2 & 1;
            int rowg = wm * 32 + mt * 16 + (lane >> 2) + s * 8;
            unsigned vmr = vmw;
            if (dt) {
                int cd = (it & 1) * 64 + rowg;
                if ((cd >> 5) == wn) vmr &= ~(1u << (cd & 31));
            }
            unsigned pmr = (labi_[r2] >= 0) ? (posm[labi_[r2] * 4 + wn] & vmr) : 0u;
            float se = se_[r2], sp = sp_[r2];
            int np = np_[r2];
#pragma unroll
            for (int nt = 0; nt < 4; nt++)
#pragma unroll
                for (int cc = 0; cc < 2; cc++) {
                    int bp = nt * 8 + sh + cc;
                    float v = acc[mt][nt][s * 2 + cc] * invT;
                    float e = __expf(v - invT);
                    if ((vmr >> bp) & 1) se += e;
                    if ((pmr >> bp) & 1) { sp += v; np++; }
                }
            se_[r2] = se; sp_[r2] = sp; np_[r2] = np;
        }
        __syncthreads();
        if (jt < 7) {
            const int j0n = j0 + 128;
#pragma unroll
            for (int i = 0; i < 8; i++) {
                int u = i * 256 + tid;
                int row = u >> 4, k8 = u & 15;
                unsigned off = (unsigned)((k8 >> 3) * 16384) +
                               sw128((unsigned)(row * 128 + (k8 & 7) * 16));
                CP16(sb + SM2_B + off, eb + (size_t)(j0n + row) * PP + k8 * 8);
            }
            CP_COMMIT();
        }
    }

    if (it == 0) {
        int cm = 0, cv = 0;
#pragma unroll
        for (int q = 0; q < 4; q++) {
            int row = q * 256 + tid;
            int mm = amask[b * LL + row];
            int lb = labels[b * LL + row];
            cm += (mm != 0);
            cv += (mm != 0) && (lb != -100);
        }
#pragma unroll
        for (int o = 16; o >= 1; o >>= 1) {
            cm += __shfl_xor_sync(0xffffffffu, cm, o);
            cv += __shfl_xor_sync(0xffffffffu, cv, o);
        }
        if (lane == 0) { cnt[wid * 2] = cm; cnt[wid * 2 + 1] = cv; }
    }

#pragma unroll
    for (int o = 1; o <= 2; o <<= 1)
#pragma unroll
        for (int r2 = 0; r2 < 4; r2++) {
            se_[r2] += __shfl_xor_sync(0xffffffffu, se_[r2], o);
            sp_[r2] += __shfl_xor_sync(0xffffffffu, sp_[r2], o);
            np_[r2] += __shfl_xor_sync(0xffffffffu, np_[r2], o);
        }
    if ((lane & 3) == 0) {
#pragma unroll
        for (int r2 = 0; r2 < 4; r2++) {
            int rowg = wm * 32 + (r2 >> 1) * 16 + (lane >> 2) + (r2 & 1) * 8;
            *(float4*)(sm + SM2_RED + (wn * 64 + rowg) * 16) =
                make_float4(se_[r2], sp_[r2], (float)np_[r2], 0.f);
        }
    }
    __syncthreads();
    float alsum = 0.f;
    if (wn == 0 && (lane & 3) == 0) {
#pragma unroll
        for (int r2 = 0; r2 < 4; r2++) {
            int rowg = wm * 32 + (r2 >> 1) * 16 + (lane >> 2) + (r2 & 1) * 8;
            float se = 0.f, sp = 0.f, np = 0.f;
#pragma unroll
            for (int w = 0; w < 4; w++) {
                float4 q = *(const float4*)(sm + SM2_RED + (w * 64 + rowg) * 16);
                se += q.x; sp += q.y; np += q.z;
            }
            alsum += (sp - np * (invT + __logf(se + 1e-12f))) / (np + 1e-12f);
        }
    }
    if (wn == 0) {
#pragma unroll
        for (int o = 16; o >= 1; o >>= 1)
            alsum += __shfl_xor_sync(0xffffffffu, alsum, o);
        if (lane == 0) wpart[wid] = alsum;
    }
    __syncthreads();
    if (tid == 0) {
        g_partial[blockIdx.x] = wpart[0] + wpart[1];
        if (it == 0) {
            int tm = 0, tv = 0;
#pragma unroll
            for (int w = 0; w < 8; w++) { tm += cnt[w * 2]; tv += cnt[w * 2 + 1]; }
            g_counts[b] = make_int2(tm, tv);
        }
    }
}

// ---------------------------------------------------------------------------
// Kernel 3: tiny deterministic final reduction
// ---------------------------------------------------------------------------
__global__ void kern_final(float* __restrict__ out) {
    __shared__ float lossb[32];
    __shared__ int okb[32];
    const int w = threadIdx.x >> 5;
    const int lane = threadIdx.x & 31;
    float ps = (lane < 16) ? g_partial[w * 16 + lane] : 0.f;
#pragma unroll
    for (int o = 8; o >= 1; o >>= 1) ps += __shfl_xor_sync(0xffffffffu, ps, o);
    if (lane == 0) {
        int2 c = g_counts[w];
        int ok = (c.x >= 2);
        float nv = (float)(c.y >= 1 ? c.y : 1);
        lossb[w] = ok ? (-ps / nv) : 0.f;
        okb[w] = ok;
    }
    __syncthreads();
    if (threadIdx.x == 0) {
        float s = 0.f;
        int ns = 0;
        for (int bq = 0; bq < 32; bq++) { s += lossb[bq]; ns += okb[bq]; }
        out[0] = s / (float)(ns > 0 ? ns : 1);
    }
}

// ---------------------------------------------------------------------------
extern "C" void kernel_launch(void* const* d_in, const int* in_sizes, int n_in,
                              void* d_out, int out_size) {
    const float* hid = (const float*)d_in[0];
    const float* W = (const float*)d_in[1];
    const float* bias = (const float*)d_in[2];
    const int* amask = (const int*)d_in[3];
    const int* labels = (const int*)d_in[4];
    float* out = (float*)d_out;

    cudaFuncSetAttribute(kern_proj, cudaFuncAttributeMaxDynamicSharedMemorySize, PROJ_SMEM);
    cudaFuncSetAttribute(kern_sim, cudaFuncAttributeMaxDynamicSharedMemorySize, SIM_SMEM);

    // 6-launch period; capture slot = position 3 -> kern_proj this round
    kern_nop<<<1, 32>>>();                                         // 0
    kern_nop<<<1, 32>>>();                                         // 1
    kern_wt<<<(HH * PP + 255) / 256, 256>>>(W);                    // 2
    kern_proj<<<NROWS / 64, 256, PROJ_SMEM>>>(hid, bias);          // 3 (ncu)
    kern_sim<<<BB * 16, 256, SIM_SMEM>>>(amask, labels);           // 4
    kern_final<<<1, 1024>>>(out);                                  // 5
}

// round 11
// speedup vs baseline: 1.2262x; 1.2262x over previous
#include <cuda_runtime.h>
#include <cuda_fp16.h>

#define BB 32
#define LL 1024
#define HH 1280
#define PP 128
#define NROWS (BB * LL)

// ---------------------------------------------------------------------------
// Helpers
// ---------------------------------------------------------------------------
__device__ __forceinline__ unsigned smem_to_u32(const void* p) {
    unsigned a;
    asm("{ .reg .u64 t; cvta.to.shared.u64 t, %1; cvt.u32.u64 %0, t; }" : "=r"(a) : "l"(p));
    return a;
}
static __device__ __forceinline__ unsigned sw128(unsigned off) {
    return off ^ ((off >> 3) & 0x70);
}
__device__ __forceinline__ unsigned f16pack(float lo, float hi) {
    unsigned r;
    asm("cvt.rn.f16x2.f32 %0, %1, %2;" : "=r"(r) : "f"(hi), "f"(lo));
    return r;
}

#define LDSM4(r0, r1, r2, r3, addr)                                          \
    asm volatile("ldmatrix.sync.aligned.m8n8.x4.shared.b16 {%0,%1,%2,%3}, [%4];" \
                 : "=r"(r0), "=r"(r1), "=r"(r2), "=r"(r3) : "r"(addr))

#define MMA(d, a, b)                                                         \
    asm volatile("mma.sync.aligned.m16n8k16.row.col.f32.f16.f16.f32 "        \
                 "{%0,%1,%2,%3},{%4,%5,%6,%7},{%8,%9},{%0,%1,%2,%3};"        \
                 : "+f"((d)[0]), "+f"((d)[1]), "+f"((d)[2]), "+f"((d)[3])    \
                 : "r"((a)[0]), "r"((a)[1]), "r"((a)[2]), "r"((a)[3]),       \
                   "r"((b)[0]), "r"((b)[1]))

#define CP16(dst, src) \
    asm volatile("cp.async.cg.shared.global [%0], [%1], 16;" :: "r"(dst), "l"(src))
#define CP_COMMIT() asm volatile("cp.async.commit_group;" ::: "memory")
#define CP_WAIT0()  asm volatile("cp.async.wait_group 0;" ::: "memory")

// ---------------------------------------------------------------------------
// Device scratch
// ---------------------------------------------------------------------------
__device__ __align__(16) __half g_emb[NROWS * PP];
__device__ __align__(16) __half g_wt[PP * HH];   // [n][k] K-major
__device__ float g_partial[BB * 16];
__device__ int2 g_counts[BB];

// ---------------------------------------------------------------------------
// Kernel 0: W -> fp16, transposed to [n][k]
// ---------------------------------------------------------------------------
__global__ void kern_wt(const float* __restrict__ W) {
    int i = blockIdx.x * 256 + threadIdx.x;
    if (i >= HH * PP) return;
    int k = i / PP, n = i % PP;
    g_wt[n * HH + k] = __float2half_rn(W[i]);
}

__global__ void kern_nop() {}

// ---------------------------------------------------------------------------
// Kernel 1: proj + L2-normalize. M=128 rows/CTA (256 CTAs), occ 2,
// A AND B double-buffered, ONE barrier per k-chunk.
// smem: bias @0, ssbuf @512, A bufs @2048+b*16384, B bufs @34816+b*16384
// ---------------------------------------------------------------------------
#define P_A(b) (2048 + (b) * 16384)
#define P_B(b) (34816 + (b) * 16384)
#define PROJ_SMEM 67584

__global__ __launch_bounds__(256, 2)
void kern_proj(const float* __restrict__ hid, const float* __restrict__ bias) {
    extern __shared__ char sm[];
    const unsigned sb = smem_to_u32(sm);
    const int tid = threadIdx.x, lane = tid & 31, wid = tid >> 5;
    const int wm = wid & 3, wn = wid >> 2;
    const int m0 = wm * 32, n0 = wn * 64;
    const int row0 = blockIdx.x * 128;
    float* bias_s = (float*)sm;
    float* ssbuf = (float*)(sm + 512);

    if (tid < 128) bias_s[tid] = bias[tid];

    float acc[2][8][4];
#pragma unroll
    for (int mt = 0; mt < 2; mt++)
#pragma unroll
        for (int nt = 0; nt < 8; nt++)
#pragma unroll
            for (int e = 0; e < 4; e++) acc[mt][nt][e] = 0.f;

    // ---- prologue: B0 cp.async; A0 LDG+convert+store into A(0) ----
#pragma unroll
    for (int i = 0; i < 4; i++) {
        int u = i * 256 + tid;
        int n = u >> 3, k8 = u & 7;
        CP16(sb + P_B(0) + sw128((unsigned)(n * 128 + k8 * 16)),
             g_wt + (size_t)n * HH + k8 * 8);
    }
    CP_COMMIT();
#pragma unroll
    for (int q = 0; q < 4; q++) {
        int u = q * 256 + tid;
        int row = u >> 3, k8 = u & 7;
        const float* s = hid + (size_t)(row0 + row) * HH + k8 * 8;
        float4 v0 = *(const float4*)s;
        float4 v1 = *(const float4*)(s + 4);
        uint4 ra = make_uint4(f16pack(v0.x, v0.y), f16pack(v0.z, v0.w),
                              f16pack(v1.x, v1.y), f16pack(v1.z, v1.w));
        *(uint4*)(sm + P_A(0) + sw128((unsigned)(row * 128 + k8 * 16))) = ra;
    }
    CP_WAIT0();
    __syncthreads();

#pragma unroll 1
    for (int c = 0; c < 20; c++) {
        const int buf = c & 1;
        float4 va[8];
        if (c < 19) {
            const int k0n = (c + 1) * 64;
            // raw A prefetch (consumed after mainloop; no cvt stall here)
#pragma unroll
            for (int q = 0; q < 4; q++) {
                int u = q * 256 + tid;
                int row = u >> 3, k8 = u & 7;
                const float* s = hid + (size_t)(row0 + row) * HH + k0n + k8 * 8;
                va[2 * q] = *(const float4*)s;
                va[2 * q + 1] = *(const float4*)(s + 4);
            }
#pragma unroll
            for (int i = 0; i < 4; i++) {
                int u = i * 256 + tid;
                int n = u >> 3, k8 = u & 7;
                CP16(sb + P_B(buf ^ 1) + sw128((unsigned)(n * 128 + k8 * 16)),
                     g_wt + (size_t)n * HH + k0n + k8 * 8);
            }
            CP_COMMIT();
        }

        const unsigned a_base = sb + P_A(buf);
        const unsigned b_base = sb + P_B(buf);
#pragma unroll
        for (int kk = 0; kk < 4; kk++) {
            unsigned ah[2][4], bh[8][2];
#pragma unroll
            for (int mt = 0; mt < 2; mt++) {
                unsigned r = m0 + mt * 16 + (lane & 15);
                unsigned off = sw128(r * 128 + kk * 32 + ((lane >> 4) << 4));
                LDSM4(ah[mt][0], ah[mt][1], ah[mt][2], ah[mt][3], a_base + off);
            }
#pragma unroll
            for (int p = 0; p < 4; p++) {
                unsigned q = lane >> 3;
                unsigned nr = n0 + p * 16 + ((q >> 1) << 3) + (lane & 7);
                unsigned off = sw128(nr * 128 + kk * 32 + ((q & 1) << 4));
                unsigned t0, t1, t2, t3;
                LDSM4(t0, t1, t2, t3, b_base + off);
                bh[2 * p][0] = t0; bh[2 * p][1] = t1;
                bh[2 * p + 1][0] = t2; bh[2 * p + 1][1] = t3;
            }
#pragma unroll
            for (int mt = 0; mt < 2; mt++)
#pragma unroll
                for (int nt = 0; nt < 8; nt++)
                    MMA(acc[mt][nt], ah[mt], bh[nt]);
        }

        if (c < 19) {
            // convert + store next A into buf^1 (readers of buf^1 finished
            // before the barrier at the end of the previous iteration)
#pragma unroll
            for (int q = 0; q < 4; q++) {
                int u = q * 256 + tid;
                int row = u >> 3, k8 = u & 7;
                uint4 ra = make_uint4(
                    f16pack(va[2 * q].x, va[2 * q].y),
                    f16pack(va[2 * q].z, va[2 * q].w),
                    f16pack(va[2 * q + 1].x, va[2 * q + 1].y),
                    f16pack(va[2 * q + 1].z, va[2 * q + 1].w));
                *(uint4*)(sm + P_A(buf ^ 1) + sw128((unsigned)(row * 128 + k8 * 16))) = ra;
            }
            CP_WAIT0();   // B(c+1) had the whole mainloop to land
        }
        __syncthreads();
    }

    // ---- epilogue: bias, L2 norm, store fp16 emb ----
    float ss[4] = {0.f, 0.f, 0.f, 0.f};
#pragma unroll
    for (int mt = 0; mt < 2; mt++)
#pragma unroll
        for (int nt = 0; nt < 8; nt++)
#pragma unroll
            for (int e = 0; e < 4; e++) {
                int s = e >> 1;
                int col = n0 + nt * 8 + (lane & 3) * 2 + (e & 1);
                float v = acc[mt][nt][e] + bias_s[col];
                acc[mt][nt][e] = v;
                ss[mt * 2 + s] += v * v;
            }
#pragma unroll
    for (int r2 = 0; r2 < 4; r2++) {
        ss[r2] += __shfl_xor_sync(0xffffffffu, ss[r2], 1);
        ss[r2] += __shfl_xor_sync(0xffffffffu, ss[r2], 2);
    }
    if ((lane & 3) == 0) {
#pragma unroll
        for (int r2 = 0; r2 < 4; r2++) {
            int rowg = wm * 32 + (r2 >> 1) * 16 + (lane >> 2) + (r2 & 1) * 8;
            ssbuf[wn * 128 + rowg] = ss[r2];
        }
    }
    __syncthreads();
#pragma unroll
    for (int r2 = 0; r2 < 4; r2++) {
        int mt = r2 >> 1, s = r2 & 1;
        int rowg = wm * 32 + mt * 16 + (lane >> 2) + s * 8;
        float tot = ssbuf[rowg] + ssbuf[128 + rowg];
        float inv = rsqrtf(tot);
        inv = inv * (1.5f - 0.5f * tot * inv * inv);
        __half* oh = g_emb + (size_t)(row0 + rowg) * PP;
#pragma unroll
        for (int nt = 0; nt < 8; nt++) {
            int col = n0 + nt * 8 + (lane & 3) * 2;
            *(unsigned*)(oh + col) =
                f16pack(acc[mt][nt][s * 2] * inv, acc[mt][nt][s * 2 + 1] * inv);
        }
    }
}

// ---------------------------------------------------------------------------
// Kernel 2: fused sim-HMMA + contrastive stats.
// M=64 rows/CTA (512 CTAs), N=64 j-tiles (16), B double-buffered (2x16KB),
// one barrier per tile, occ 4 single wave. Masks parity-double-buffered.
// ---------------------------------------------------------------------------
#define SM2_WPART 0
#define SM2_MASK  64      // valm[2][2] @64..80, posm[2][8] @80..144
#define SM2_CNT   160
#define SM2_RED   256
#define SM2_A     5120
#define SM2_B(b)  (21504 + (b) * 16384)
#define SIM_SMEM  54272

__global__ __launch_bounds__(256, 4)
void kern_sim(const int* __restrict__ amask, const int* __restrict__ labels) {
    extern __shared__ char sm[];
    const unsigned sb = smem_to_u32(sm);
    const int tid = threadIdx.x, lane = tid & 31, wid = tid >> 5;
    const int wm = wid & 1, wn = wid >> 1;          // wn 0..3
    const int m0 = wm * 32, n0 = wn * 16;
    const int b = blockIdx.x >> 4, it = blockIdx.x & 15;
    const int i0 = it * 64;
    const __half* eb = g_emb + (size_t)b * LL * PP;
    float* wpart = (float*)(sm + SM2_WPART);
    unsigned* valm = (unsigned*)(sm + SM2_MASK);    // [parity*2 + word]
    unsigned* posm = valm + 4;                      // [parity*8 + l*2 + word]
    int* cnt = (int*)(sm + SM2_CNT);
    const int wword = wn >> 1;                      // this warp's mask word
    const int wbase = (wn & 1) * 16;                // bit base within word

    // A tile (64 rows x 128k): 4 CP16/thread
#pragma unroll
    for (int i = 0; i < 4; i++) {
        int u = i * 256 + tid;
        int row = u >> 4, k8 = u & 15;
        unsigned off = (unsigned)((k8 >> 3) * 8192) +
                       sw128((unsigned)(row * 128 + (k8 & 7) * 16));
        CP16(sb + SM2_A + off, eb + (size_t)(i0 + row) * PP + k8 * 8);
    }
    // B tile 0 (64 rows x 128k): 4 CP16/thread
#pragma unroll
    for (int i = 0; i < 4; i++) {
        int u = i * 256 + tid;
        int row = u >> 4, k8 = u & 15;
        unsigned off = (unsigned)((k8 >> 3) * 8192) +
                       sw128((unsigned)(row * 128 + (k8 & 7) * 16));
        CP16(sb + SM2_B(0) + off, eb + (size_t)row * PP + k8 * 8);
    }
    CP_COMMIT();

    int labi_[4], np_[4];
    float se_[4], sp_[4];
#pragma unroll
    for (int r2 = 0; r2 < 4; r2++) {
        int rowg = wm * 32 + (r2 >> 1) * 16 + (lane >> 2) + (r2 & 1) * 8;
        int gi = i0 + rowg;
        int lb = labels[b * LL + gi];
        labi_[r2] = ((amask[b * LL + gi] != 0) && (lb != -100)) ? lb : -1;
        se_[r2] = 0.f; sp_[r2] = 0.f; np_[r2] = 0;
    }
    const float invT = 1.0f / 0.07f;

#pragma unroll 1
    for (int jt = 0; jt < 16; jt++) {
        const int buf = jt & 1;
        const int par = jt & 1;
        const int j0 = jt * 64;
        // masks for this tile (warps 0-1 cover the 64 columns)
        if (tid < 64) {
            int mm = amask[b * LL + j0 + tid];
            int lb = labels[b * LL + j0 + tid];
            int vv = (mm != 0) && (lb != -100);
            unsigned vmb = __ballot_sync(0xffffffffu, vv);
            if (lane == 0) valm[par * 2 + wid] = vmb;
#pragma unroll
            for (int l = 0; l < 4; l++) {
                unsigned pb = __ballot_sync(0xffffffffu, vv && (lb == l));
                if (lane == 0) posm[par * 8 + l * 2 + wid] = pb;
            }
        }
        CP_WAIT0();       // only the current tile's group is in flight here
        __syncthreads();  // mask + B(buf) visible; buf^1 readers all done

        float acc[2][2][4];
#pragma unroll
        for (int mt = 0; mt < 2; mt++)
#pragma unroll
            for (int nt = 0; nt < 2; nt++)
#pragma unroll
                for (int e = 0; e < 4; e++) acc[mt][nt][e] = 0.f;

        const unsigned b_base = sb + SM2_B(buf);
#pragma unroll
        for (int kk = 0; kk < 8; kk++) {
            const unsigned ch = (unsigned)((kk >> 2) * 8192);
            const unsigned kk2 = (kk & 3) * 32;
            unsigned ah[2][4], bh[2][2];
#pragma unroll
            for (int mt = 0; mt < 2; mt++) {
                unsigned r = m0 + mt * 16 + (lane & 15);
                unsigned off = ch + sw128(r * 128 + kk2 + ((lane >> 4) << 4));
                LDSM4(ah[mt][0], ah[mt][1], ah[mt][2], ah[mt][3], sb + SM2_A + off);
            }
            {
                unsigned q = lane >> 3;
                unsigned nr = n0 + ((q >> 1) << 3) + (lane & 7);
                unsigned off = ch + sw128(nr * 128 + kk2 + ((q & 1) << 4));
                unsigned t0, t1, t2, t3;
                LDSM4(t0, t1, t2, t3, b_base + off);
                bh[0][0] = t0; bh[0][1] = t1;
                bh[1][0] = t2; bh[1][1] = t3;
            }
#pragma unroll
            for (int mt = 0; mt < 2; mt++)
#pragma unroll
                for (int nt = 0; nt < 2; nt++)
                    MMA(acc[mt][nt], ah[mt], bh[nt]);
        }

        // issue next B tile into buf^1 (overlaps with epilogue below)
        if (jt < 15) {
            const int j0n = j0 + 64;
#pragma unroll
            for (int i = 0; i < 4; i++) {
                int u = i * 256 + tid;
                int row = u >> 4, k8 = u & 15;
                unsigned off = (unsigned)((k8 >> 3) * 8192) +
                               sw128((unsigned)(row * 128 + (k8 & 7) * 16));
                CP16(sb + SM2_B(buf ^ 1) + off, eb + (size_t)(j0n + row) * PP + k8 * 8);
            }
            CP_COMMIT();
        }

        // fixed-shift epilogue, bitmask-gated
        const unsigned vmw = valm[par * 2 + wword];
        const int dt = (jt == it);
        const int sh = (lane & 3) * 2;
#pragma unroll
        for (int r2 = 0; r2 < 4; r2++) {
            int mt = r2 >> 1, s = r2 & 1;
            int rowg = wm * 32 + mt * 16 + (lane >> 2) + s * 8;
            unsigned vmr = vmw;
            if (dt && ((rowg >> 5) == wword)) vmr &= ~(1u << (rowg & 31));
            unsigned pmr = (labi_[r2] >= 0)
                               ? (posm[par * 8 + labi_[r2] * 2 + wword] & vmr) : 0u;
            float se = se_[r2], sp = sp_[r2];
            int np = np_[r2];
#pragma unroll
            for (int nt = 0; nt < 2; nt++)
#pragma unroll
                for (int cc = 0; cc < 2; cc++) {
                    int bp = wbase + nt * 8 + sh + cc;
                    float v = acc[mt][nt][s * 2 + cc] * invT;
                    float e = __expf(v - invT);
                    if ((vmr >> bp) & 1) se += e;
                    if ((pmr >> bp) & 1) { sp += v; np++; }
                }
            se_[r2] = se; sp_[r2] = sp; np_[r2] = np;
        }
    }

    // per-batch counts (it==0 CTAs)
    if (it == 0) {
        int cm = 0, cv = 0;
#pragma unroll
        for (int q = 0; q < 4; q++) {
            int row = q * 256 + tid;
            int mm = amask[b * LL + row];
            int lb = labels[b * LL + row];
            cm += (mm != 0);
            cv += (mm != 0) && (lb != -100);
        }
#pragma unroll
        for (int o = 16; o >= 1; o >>= 1) {
            cm += __shfl_xor_sync(0xffffffffu, cm, o);
            cv += __shfl_xor_sync(0xffffffffu, cv, o);
        }
        if (lane == 0) { cnt[wid * 2] = cm; cnt[wid * 2 + 1] = cv; }
    }

    // merge stats: 4 lanes per row, then 4 wn groups via smem
#pragma unroll
    for (int o = 1; o <= 2; o <<= 1)
#pragma unroll
        for (int r2 = 0; r2 < 4; r2++) {
            se_[r2] += __shfl_xor_sync(0xffffffffu, se_[r2], o);
            sp_[r2] += __shfl_xor_sync(0xffffffffu, sp_[r2], o);
            np_[r2] += __shfl_xor_sync(0xffffffffu, np_[r2], o);
        }
    __syncthreads();   // protect mask/red smem reuse + ensure mainloop done
    if ((lane & 3) == 0) {
#pragma unroll
        for (int r2 = 0; r2 < 4; r2++) {
            int rowg = wm * 32 + (r2 >> 1) * 16 + (lane >> 2) + (r2 & 1) * 8;
            *(float4*)(sm + SM2_RED + (wn * 64 + rowg) * 16) =
                make_float4(se_[r2], sp_[r2], (float)np_[r2], 0.f);
        }
    }
    __syncthreads();
    float alsum = 0.f;
    if (wn == 0 && (lane & 3) == 0) {
#pragma unroll
        for (int r2 = 0; r2 < 4; r2++) {
            int rowg = wm * 32 + (r2 >> 1) * 16 + (lane >> 2) + (r2 & 1) * 8;
            float se = 0.f, sp = 0.f, np = 0.f;
#pragma unroll
            for (int w = 0; w < 4; w++) {
                float4 q = *(const float4*)(sm + SM2_RED + (w * 64 + rowg) * 16);
                se += q.x; sp += q.y; np += q.z;
            }
            alsum += (sp - np * (invT + __logf(se + 1e-12f))) / (np + 1e-12f);
        }
    }
    if (wn == 0) {
#pragma unroll
        for (int o = 16; o >= 1; o >>= 1)
            alsum += __shfl_xor_sync(0xffffffffu, alsum, o);
        if (lane == 0) wpart[wid] = alsum;
    }
    __syncthreads();
    if (tid == 0) {
        g_partial[blockIdx.x] = wpart[0] + wpart[1];
        if (it == 0) {
            int tm = 0, tv = 0;
#pragma unroll
            for (int w = 0; w < 8; w++) { tm += cnt[w * 2]; tv += cnt[w * 2 + 1]; }
            g_counts[b] = make_int2(tm, tv);
        }
    }
}

// ---------------------------------------------------------------------------
// Kernel 3: tiny deterministic final reduction
// ---------------------------------------------------------------------------
__global__ void kern_final(float* __restrict__ out) {
    __shared__ float lossb[32];
    __shared__ int okb[32];
    const int w = threadIdx.x >> 5;
    const int lane = threadIdx.x & 31;
    float ps = (lane < 16) ? g_partial[w * 16 + lane] : 0.f;
#pragma unroll
    for (int o = 8; o >= 1; o >>= 1) ps += __shfl_xor_sync(0xffffffffu, ps, o);
    if (lane == 0) {
        int2 c = g_counts[w];
        int ok = (c.x >= 2);
        float nv = (float)(c.y >= 1 ? c.y : 1);
        lossb[w] = ok ? (-ps / nv) : 0.f;
        okb[w] = ok;
    }
    __syncthreads();
    if (threadIdx.x == 0) {
        float s = 0.f;
        int ns = 0;
        for (int bq = 0; bq < 32; bq++) { s += lossb[bq]; ns += okb[bq]; }
        out[0] = s / (float)(ns > 0 ? ns : 1);
    }
}

// ---------------------------------------------------------------------------
extern "C" void kernel_launch(void* const* d_in, const int* in_sizes, int n_in,
                              void* d_out, int out_size) {
    const float* hid = (const float*)d_in[0];
    const float* W = (const float*)d_in[1];
    const float* bias = (const float*)d_in[2];
    const int* amask = (const int*)d_in[3];
    const int* labels = (const int*)d_in[4];
    float* out = (float*)d_out;

    cudaFuncSetAttribute(kern_proj, cudaFuncAttributeMaxDynamicSharedMemorySize, PROJ_SMEM);
    cudaFuncSetAttribute(kern_sim, cudaFuncAttributeMaxDynamicSharedMemorySize, SIM_SMEM);

    // capture slot = launch index 3 -> kern_sim this round
    kern_wt<<<(HH * PP + 255) / 256, 256>>>(W);                    // 0
    kern_proj<<<NROWS / 128, 256, PROJ_SMEM>>>(hid, bias);         // 1
    kern_nop<<<1, 32>>>();                                         // 2
    kern_sim<<<BB * 16, 256, SIM_SMEM>>>(amask, labels);           // 3 (ncu)
    kern_final<<<1, 1024>>>(out);                                  // 4
    kern_nop<<<1, 32>>>();                                         // 5
}

// round 12
// speedup vs baseline: 1.3243x; 1.0800x over previous
#include <cuda_runtime.h>
#include <cuda_fp16.h>

#define BB 32
#define LL 1024
#define HH 1280
#define PP 128
#define NROWS (BB * LL)
#define INVT 14.285714285714286f
#define C1F (14.285714285714286f * 1.4426950408889634f)

// ---------------------------------------------------------------------------
// Helpers
// ---------------------------------------------------------------------------
__device__ __forceinline__ unsigned smem_to_u32(const void* p) {
    unsigned a;
    asm("{ .reg .u64 t; cvta.to.shared.u64 t, %1; cvt.u32.u64 %0, t; }" : "=r"(a) : "l"(p));
    return a;
}
static __device__ __forceinline__ unsigned sw128(unsigned off) {
    return off ^ ((off >> 3) & 0x70);
}
__device__ __forceinline__ float ex2f(float x) {
    float r;
    asm("ex2.approx.f32 %0, %1;" : "=f"(r) : "f"(x));
    return r;
}
__device__ __forceinline__ unsigned f16pack(float lo, float hi) {
    unsigned r;
    asm("cvt.rn.f16x2.f32 %0, %1, %2;" : "=r"(r) : "f"(hi), "f"(lo));
    return r;
}

#define LDSM4(r0, r1, r2, r3, addr)                                          \
    asm volatile("ldmatrix.sync.aligned.m8n8.x4.shared.b16 {%0,%1,%2,%3}, [%4];" \
                 : "=r"(r0), "=r"(r1), "=r"(r2), "=r"(r3) : "r"(addr))

#define MMA(d, a, b)                                                         \
    asm volatile("mma.sync.aligned.m16n8k16.row.col.f32.f16.f16.f32 "        \
                 "{%0,%1,%2,%3},{%4,%5,%6,%7},{%8,%9},{%0,%1,%2,%3};"        \
                 : "+f"((d)[0]), "+f"((d)[1]), "+f"((d)[2]), "+f"((d)[3])    \
                 : "r"((a)[0]), "r"((a)[1]), "r"((a)[2]), "r"((a)[3]),       \
                   "r"((b)[0]), "r"((b)[1]))

#define CP16(dst, src) \
    asm volatile("cp.async.cg.shared.global [%0], [%1], 16;" :: "r"(dst), "l"(src))
#define CP_COMMIT() asm volatile("cp.async.commit_group;" ::: "memory")
#define CP_WAIT0()  asm volatile("cp.async.wait_group 0;" ::: "memory")

// ---------------------------------------------------------------------------
// Device scratch
// ---------------------------------------------------------------------------
__device__ __align__(16) __half g_emb[NROWS * PP];
__device__ __align__(16) __half g_wt[PP * HH];   // [n][k] K-major
__device__ float g_partial[BB * 16];
__device__ int2 g_counts[BB];
__device__ int g_done = 0;

// ---------------------------------------------------------------------------
// Kernel 0: W -> fp16, transposed to [n][k]
// ---------------------------------------------------------------------------
__global__ void kern_wt(const float* __restrict__ W) {
    int i = blockIdx.x * 256 + threadIdx.x;
    if (i >= HH * PP) return;
    int k = i / PP, n = i % PP;
    g_wt[n * HH + k] = __float2half_rn(W[i]);
}

// ---------------------------------------------------------------------------
// Kernel 1: proj + L2-normalize; invalid rows stored as ZERO (enables
// maskless se in kern_sim). M=128/CTA, A+B double-buffered, 1 sync/chunk.
// ---------------------------------------------------------------------------
#define P_A(b) (2048 + (b) * 16384)
#define P_B(b) (34816 + (b) * 16384)
#define PROJ_SMEM 67584

__global__ __launch_bounds__(256, 2)
void kern_proj(const float* __restrict__ hid, const float* __restrict__ bias,
               const int* __restrict__ amask, const int* __restrict__ labels) {
    extern __shared__ char sm[];
    const unsigned sb = smem_to_u32(sm);
    const int tid = threadIdx.x, lane = tid & 31, wid = tid >> 5;
    const int wm = wid & 3, wn = wid >> 2;
    const int m0 = wm * 32, n0 = wn * 64;
    const int row0 = blockIdx.x * 128;
    float* bias_s = (float*)sm;
    float* ssbuf = (float*)(sm + 512);

    if (tid < 128) bias_s[tid] = bias[tid];

    float acc[2][8][4];
#pragma unroll
    for (int mt = 0; mt < 2; mt++)
#pragma unroll
        for (int nt = 0; nt < 8; nt++)
#pragma unroll
            for (int e = 0; e < 4; e++) acc[mt][nt][e] = 0.f;

#pragma unroll
    for (int i = 0; i < 4; i++) {
        int u = i * 256 + tid;
        int n = u >> 3, k8 = u & 7;
        CP16(sb + P_B(0) + sw128((unsigned)(n * 128 + k8 * 16)),
             g_wt + (size_t)n * HH + k8 * 8);
    }
    CP_COMMIT();
#pragma unroll
    for (int q = 0; q < 4; q++) {
        int u = q * 256 + tid;
        int row = u >> 3, k8 = u & 7;
        const float* s = hid + (size_t)(row0 + row) * HH + k8 * 8;
        float4 v0 = *(const float4*)s;
        float4 v1 = *(const float4*)(s + 4);
        uint4 ra = make_uint4(f16pack(v0.x, v0.y), f16pack(v0.z, v0.w),
                              f16pack(v1.x, v1.y), f16pack(v1.z, v1.w));
        *(uint4*)(sm + P_A(0) + sw128((unsigned)(row * 128 + k8 * 16))) = ra;
    }
    CP_WAIT0();
    __syncthreads();

#pragma unroll 1
    for (int c = 0; c < 20; c++) {
        const int buf = c & 1;
        float4 va[8];
        if (c < 19) {
            const int k0n = (c + 1) * 64;
#pragma unroll
            for (int q = 0; q < 4; q++) {
                int u = q * 256 + tid;
                int row = u >> 3, k8 = u & 7;
                const float* s = hid + (size_t)(row0 + row) * HH + k0n + k8 * 8;
                va[2 * q] = *(const float4*)s;
                va[2 * q + 1] = *(const float4*)(s + 4);
            }
#pragma unroll
            for (int i = 0; i < 4; i++) {
                int u = i * 256 + tid;
                int n = u >> 3, k8 = u & 7;
                CP16(sb + P_B(buf ^ 1) + sw128((unsigned)(n * 128 + k8 * 16)),
                     g_wt + (size_t)n * HH + k0n + k8 * 8);
            }
            CP_COMMIT();
        }

        const unsigned a_base = sb + P_A(buf);
        const unsigned b_base = sb + P_B(buf);
#pragma unroll
        for (int kk = 0; kk < 4; kk++) {
            unsigned ah[2][4], bh[8][2];
#pragma unroll
            for (int mt = 0; mt < 2; mt++) {
                unsigned r = m0 + mt * 16 + (lane & 15);
                unsigned off = sw128(r * 128 + kk * 32 + ((lane >> 4) << 4));
                LDSM4(ah[mt][0], ah[mt][1], ah[mt][2], ah[mt][3], a_base + off);
            }
#pragma unroll
            for (int p = 0; p < 4; p++) {
                unsigned q = lane >> 3;
                unsigned nr = n0 + p * 16 + ((q >> 1) << 3) + (lane & 7);
                unsigned off = sw128(nr * 128 + kk * 32 + ((q & 1) << 4));
                unsigned t0, t1, t2, t3;
                LDSM4(t0, t1, t2, t3, b_base + off);
                bh[2 * p][0] = t0; bh[2 * p][1] = t1;
                bh[2 * p + 1][0] = t2; bh[2 * p + 1][1] = t3;
            }
#pragma unroll
            for (int mt = 0; mt < 2; mt++)
#pragma unroll
                for (int nt = 0; nt < 8; nt++)
                    MMA(acc[mt][nt], ah[mt], bh[nt]);
        }

        if (c < 19) {
#pragma unroll
            for (int q = 0; q < 4; q++) {
                int u = q * 256 + tid;
                int row = u >> 3, k8 = u & 7;
                uint4 ra = make_uint4(
                    f16pack(va[2 * q].x, va[2 * q].y),
                    f16pack(va[2 * q].z, va[2 * q].w),
                    f16pack(va[2 * q + 1].x, va[2 * q + 1].y),
                    f16pack(va[2 * q + 1].z, va[2 * q + 1].w));
                *(uint4*)(sm + P_A(buf ^ 1) + sw128((unsigned)(row * 128 + k8 * 16))) = ra;
            }
            CP_WAIT0();
        }
        __syncthreads();
    }

    // epilogue: bias, L2 norm, ZERO invalid rows, store fp16 emb
    float ss[4] = {0.f, 0.f, 0.f, 0.f};
#pragma unroll
    for (int mt = 0; mt < 2; mt++)
#pragma unroll
        for (int nt = 0; nt < 8; nt++)
#pragma unroll
            for (int e = 0; e < 4; e++) {
                int s = e >> 1;
                int col = n0 + nt * 8 + (lane & 3) * 2 + (e & 1);
                float v = acc[mt][nt][e] + bias_s[col];
                acc[mt][nt][e] = v;
                ss[mt * 2 + s] += v * v;
            }
#pragma unroll
    for (int r2 = 0; r2 < 4; r2++) {
        ss[r2] += __shfl_xor_sync(0xffffffffu, ss[r2], 1);
        ss[r2] += __shfl_xor_sync(0xffffffffu, ss[r2], 2);
    }
    if ((lane & 3) == 0) {
#pragma unroll
        for (int r2 = 0; r2 < 4; r2++) {
            int rowg = wm * 32 + (r2 >> 1) * 16 + (lane >> 2) + (r2 & 1) * 8;
            ssbuf[wn * 128 + rowg] = ss[r2];
        }
    }
    __syncthreads();
#pragma unroll
    for (int r2 = 0; r2 < 4; r2++) {
        int mt = r2 >> 1, s = r2 & 1;
        int rowg = wm * 32 + mt * 16 + (lane >> 2) + s * 8;
        int gr = row0 + rowg;
        int vv = (amask[gr] != 0) && (labels[gr] != -100);
        float tot = ssbuf[rowg] + ssbuf[128 + rowg];
        float inv = rsqrtf(tot);
        inv = inv * (1.5f - 0.5f * tot * inv * inv);
        if (!vv) inv = 0.f;
        __half* oh = g_emb + (size_t)gr * PP;
#pragma unroll
        for (int nt = 0; nt < 8; nt++) {
            int col = n0 + nt * 8 + (lane & 3) * 2;
            *(unsigned*)(oh + col) =
                f16pack(acc[mt][nt][s * 2] * inv, acc[mt][nt][s * 2 + 1] * inv);
        }
    }
}

// ---------------------------------------------------------------------------
// Kernel 2: sim-HMMA + contrastive stats; maskless se (invalid rows are 0)
// with end-correction; np via popc; sp raw. Last CTA does the final scalar.
// M=64/CTA, N=64 tiles, B double-buffered, occ 4 single wave.
// ---------------------------------------------------------------------------
#define SM2_WPART 0
#define SM2_MASK  64
#define SM2_CNT   160
#define SM2_RED   256
#define SM2_A     5120
#define SM2_B(b)  (21504 + (b) * 16384)
#define SIM_SMEM  54272

__global__ __launch_bounds__(256, 4)
void kern_sim(const int* __restrict__ amask, const int* __restrict__ labels,
              float* __restrict__ out) {
    extern __shared__ char sm[];
    __shared__ int lastf;
    const unsigned sb = smem_to_u32(sm);
    const int tid = threadIdx.x, lane = tid & 31, wid = tid >> 5;
    const int wm = wid & 1, wn = wid >> 1;
    const int m0 = wm * 32, n0 = wn * 16;
    const int b = blockIdx.x >> 4, it = blockIdx.x & 15;
    const int i0 = it * 64;
    const __half* eb = g_emb + (size_t)b * LL * PP;
    float* wpart = (float*)(sm + SM2_WPART);
    unsigned* valm = (unsigned*)(sm + SM2_MASK);    // [parity*2 + word]
    unsigned* posm = valm + 4;                      // [parity*8 + l*2 + word]
    int* cnt = (int*)(sm + SM2_CNT);
    const int wword = wn >> 1;
    const int wbase = (wn & 1) * 16;
    const int sh = (lane & 3) * 2;
    const unsigned mthr = (0x3u << (wbase + sh)) | (0x3u << (wbase + sh + 8));

#pragma unroll
    for (int i = 0; i < 4; i++) {
        int u = i * 256 + tid;
        int row = u >> 4, k8 = u & 15;
        unsigned off = (unsigned)((k8 >> 3) * 8192) +
                       sw128((unsigned)(row * 128 + (k8 & 7) * 16));
        CP16(sb + SM2_A + off, eb + (size_t)(i0 + row) * PP + k8 * 8);
    }
#pragma unroll
    for (int i = 0; i < 4; i++) {
        int u = i * 256 + tid;
        int row = u >> 4, k8 = u & 15;
        unsigned off = (unsigned)((k8 >> 3) * 8192) +
                       sw128((unsigned)(row * 128 + (k8 & 7) * 16));
        CP16(sb + SM2_B(0) + off, eb + (size_t)row * PP + k8 * 8);
    }
    CP_COMMIT();

    int labi_[4], np_[4];
    float se_[4], sp_[4];
#pragma unroll
    for (int r2 = 0; r2 < 4; r2++) {
        int rowg = wm * 32 + (r2 >> 1) * 16 + (lane >> 2) + (r2 & 1) * 8;
        int gi = i0 + rowg;
        int lb = labels[b * LL + gi];
        labi_[r2] = ((amask[b * LL + gi] != 0) && (lb != -100)) ? lb : -1;
        se_[r2] = 0.f; sp_[r2] = 0.f; np_[r2] = 0;
    }
    int nv = 0;   // total valid columns in this batch (accumulated over tiles)

#pragma unroll 1
    for (int jt = 0; jt < 16; jt++) {
        const int buf = jt & 1;
        const int par = jt & 1;
        const int j0 = jt * 64;
        if (tid < 64) {
            int mm = amask[b * LL + j0 + tid];
            int lb = labels[b * LL + j0 + tid];
            int vv = (mm != 0) && (lb != -100);
            unsigned vmb = __ballot_sync(0xffffffffu, vv);
            if (lane == 0) valm[par * 2 + wid] = vmb;
#pragma unroll
            for (int l = 0; l < 4; l++) {
                unsigned pb = __ballot_sync(0xffffffffu, vv && (lb == l));
                if (lane == 0) posm[par * 8 + l * 2 + wid] = pb;
            }
        }
        CP_WAIT0();
        __syncthreads();
        nv += __popc(valm[par * 2]) + __popc(valm[par * 2 + 1]);

        float acc[2][2][4];
#pragma unroll
        for (int mt = 0; mt < 2; mt++)
#pragma unroll
            for (int nt = 0; nt < 2; nt++)
#pragma unroll
                for (int e = 0; e < 4; e++) acc[mt][nt][e] = 0.f;

        const unsigned b_base = sb + SM2_B(buf);
#pragma unroll
        for (int kk = 0; kk < 8; kk++) {
            const unsigned ch = (unsigned)((kk >> 2) * 8192);
            const unsigned kk2 = (kk & 3) * 32;
            unsigned ah[2][4], bh[2][2];
#pragma unroll
            for (int mt = 0; mt < 2; mt++) {
                unsigned r = m0 + mt * 16 + (lane & 15);
                unsigned off = ch + sw128(r * 128 + kk2 + ((lane >> 4) << 4));
                LDSM4(ah[mt][0], ah[mt][1], ah[mt][2], ah[mt][3], sb + SM2_A + off);
            }
            {
                unsigned q = lane >> 3;
                unsigned nr = n0 + ((q >> 1) << 3) + (lane & 7);
                unsigned off = ch + sw128(nr * 128 + kk2 + ((q & 1) << 4));
                unsigned t0, t1, t2, t3;
                LDSM4(t0, t1, t2, t3, b_base + off);
                bh[0][0] = t0; bh[0][1] = t1;
                bh[1][0] = t2; bh[1][1] = t3;
            }
#pragma unroll
            for (int mt = 0; mt < 2; mt++)
#pragma unroll
                for (int nt = 0; nt < 2; nt++)
                    MMA(acc[mt][nt], ah[mt], bh[nt]);
        }

        if (jt < 15) {
            const int j0n = j0 + 64;
#pragma unroll
            for (int i = 0; i < 4; i++) {
                int u = i * 256 + tid;
                int row = u >> 4, k8 = u & 15;
                unsigned off = (unsigned)((k8 >> 3) * 8192) +
                               sw128((unsigned)(row * 128 + (k8 & 7) * 16));
                CP16(sb + SM2_B(buf ^ 1) + off, eb + (size_t)(j0n + row) * PP + k8 * 8);
            }
            CP_COMMIT();
        }

        // epilogue: maskless se; sp gated by pos-bits; np via popc
        const int dt = (jt == it);
#pragma unroll
        for (int r2 = 0; r2 < 4; r2++) {
            int mt = r2 >> 1, s = r2 & 1;
            int rowg = wm * 32 + mt * 16 + (lane >> 2) + s * 8;
            unsigned pmr = (labi_[r2] >= 0)
                               ? posm[par * 8 + labi_[r2] * 2 + wword] : 0u;
            float se = se_[r2], sp = sp_[r2];
            int np = np_[r2];
            if (dt && ((rowg >> 5) == wword)) {
                int dbp = rowg & 31;
                pmr &= ~(1u << dbp);
                np += __popc(pmr & mthr);
#pragma unroll
                for (int nt = 0; nt < 2; nt++)
#pragma unroll
                    for (int cc = 0; cc < 2; cc++) {
                        int bp = wbase + nt * 8 + sh + cc;
                        float a = acc[mt][nt][s * 2 + cc];
                        float e = ex2f(fmaf(a, C1F, -C1F));
                        se += (bp == dbp) ? 0.f : e;
                        if ((pmr >> bp) & 1) sp += a;
                    }
            } else {
                np += __popc(pmr & mthr);
#pragma unroll
                for (int nt = 0; nt < 2; nt++)
#pragma unroll
                    for (int cc = 0; cc < 2; cc++) {
                        int bp = wbase + nt * 8 + sh + cc;
                        float a = acc[mt][nt][s * 2 + cc];
                        se += ex2f(fmaf(a, C1F, -C1F));
                        if ((pmr >> bp) & 1) sp += a;
                    }
            }
            se_[r2] = se; sp_[r2] = sp; np_[r2] = np;
        }
    }

    // per-batch counts (it==0 CTAs)
    if (it == 0) {
        int cm = 0, cv = 0;
#pragma unroll
        for (int q = 0; q < 4; q++) {
            int row = q * 256 + tid;
            int mm = amask[b * LL + row];
            int lb = labels[b * LL + row];
            cm += (mm != 0);
            cv += (mm != 0) && (lb != -100);
        }
#pragma unroll
        for (int o = 16; o >= 1; o >>= 1) {
            cm += __shfl_xor_sync(0xffffffffu, cm, o);
            cv += __shfl_xor_sync(0xffffffffu, cv, o);
        }
        if (lane == 0) { cnt[wid * 2] = cm; cnt[wid * 2 + 1] = cv; }
    }

    // merge: 4 lanes/row, then 4 wn groups via smem
#pragma unroll
    for (int o = 1; o <= 2; o <<= 1)
#pragma unroll
        for (int r2 = 0; r2 < 4; r2++) {
            se_[r2] += __shfl_xor_sync(0xffffffffu, se_[r2], o);
            sp_[r2] += __shfl_xor_sync(0xffffffffu, sp_[r2], o);
            np_[r2] += __shfl_xor_sync(0xffffffffu, np_[r2], o);
        }
    __syncthreads();
    if ((lane & 3) == 0) {
#pragma unroll
        for (int r2 = 0; r2 < 4; r2++) {
            int rowg = wm * 32 + (r2 >> 1) * 16 + (lane >> 2) + (r2 & 1) * 8;
            *(float4*)(sm + SM2_RED + (wn * 64 + rowg) * 16) =
                make_float4(se_[r2], sp_[r2], (float)np_[r2], 0.f);
        }
    }
    __syncthreads();
    float alsum = 0.f;
    if (wn == 0 && (lane & 3) == 0) {
        const float corrE = ex2f(-C1F);
        const float n_inv = (float)(LL - nv);
#pragma unroll
        for (int r2 = 0; r2 < 4; r2++) {
            int rowg = wm * 32 + (r2 >> 1) * 16 + (lane >> 2) + (r2 & 1) * 8;
            float se = 0.f, sp = 0.f, np = 0.f;
#pragma unroll
            for (int w = 0; w < 4; w++) {
                float4 q = *(const float4*)(sm + SM2_RED + (w * 64 + rowg) * 16);
                se += q.x; sp += q.y; np += q.z;
            }
            float sec = se - n_inv * corrE;   // remove invalid-column exps
            alsum += (INVT * sp - np * (INVT + __logf(sec + 1e-12f))) / (np + 1e-12f);
        }
    }
    if (wn == 0) {
#pragma unroll
        for (int o = 16; o >= 1; o >>= 1)
            alsum += __shfl_xor_sync(0xffffffffu, alsum, o);
        if (lane == 0) wpart[wid] = alsum;
    }
    __syncthreads();
    if (tid == 0) {
        g_partial[blockIdx.x] = wpart[0] + wpart[1];
        if (it == 0) {
            int tm = 0, tv = 0;
#pragma unroll
            for (int w = 0; w < 8; w++) { tm += cnt[w * 2]; tv += cnt[w * 2 + 1]; }
            g_counts[b] = make_int2(tm, tv);
        }
    }

    // ---- last-CTA final scalar reduction (deterministic fixed-order sum) ----
    __threadfence();
    if (tid == 0) {
        int t = atomicAdd(&g_done, 1);
        lastf = (t == BB * 16 - 1);
    }
    __syncthreads();
    if (lastf) {
        __threadfence();
        if (tid < 32) {
            float ps = 0.f;
#pragma unroll
            for (int t = 0; t < 16; t++) ps += __ldcg(&g_partial[tid * 16 + t]);
            int2 c;
            c.x = __ldcg(&((const int*)g_counts)[tid * 2]);
            c.y = __ldcg(&((const int*)g_counts)[tid * 2 + 1]);
            int ok = (c.x >= 2);
            float nvv = (float)(c.y >= 1 ? c.y : 1);
            float lossb = ok ? (-ps / nvv) : 0.f;
            int ns = ok;
#pragma unroll
            for (int o = 16; o >= 1; o >>= 1) {
                lossb += __shfl_xor_sync(0xffffffffu, lossb, o);
                ns += __shfl_xor_sync(0xffffffffu, ns, o);
            }
            if (tid == 0) {
                out[0] = lossb / (float)(ns > 0 ? ns : 1);
                g_done = 0;   // reset for next graph replay
            }
        }
    }
}

// ---------------------------------------------------------------------------
extern "C" void kernel_launch(void* const* d_in, const int* in_sizes, int n_in,
                              void* d_out, int out_size) {
    const float* hid = (const float*)d_in[0];
    const float* W = (const float*)d_in[1];
    const float* bias = (const float*)d_in[2];
    const int* amask = (const int*)d_in[3];
    const int* labels = (const int*)d_in[4];
    float* out = (float*)d_out;

    cudaFuncSetAttribute(kern_proj, cudaFuncAttributeMaxDynamicSharedMemorySize, PROJ_SMEM);
    cudaFuncSetAttribute(kern_sim, cudaFuncAttributeMaxDynamicSharedMemorySize, SIM_SMEM);

    kern_wt<<<(HH * PP + 255) / 256, 256>>>(W);                        // 0
    kern_proj<<<NROWS / 128, 256, PROJ_SMEM>>>(hid, bias, amask, labels); // 1
    kern_sim<<<BB * 16, 256, SIM_SMEM>>>(amask, labels, out);          // 2
}

// round 13
// speedup vs baseline: 1.3696x; 1.0342x over previous
#include <cuda_runtime.h>
#include <cuda_fp16.h>

#define BB 32
#define LL 1024
#define HH 1280
#define PP 128
#define NROWS (BB * LL)
#define INVT 14.285714285714286f
#define C1F (14.285714285714286f * 1.4426950408889634f)

// ---------------------------------------------------------------------------
// Helpers
// ---------------------------------------------------------------------------
__device__ __forceinline__ unsigned smem_to_u32(const void* p) {
    unsigned a;
    asm("{ .reg .u64 t; cvta.to.shared.u64 t, %1; cvt.u32.u64 %0, t; }" : "=r"(a) : "l"(p));
    return a;
}
static __device__ __forceinline__ unsigned sw128(unsigned off) {
    return off ^ ((off >> 3) & 0x70);
}
__device__ __forceinline__ float ex2f(float x) {
    float r;
    asm("ex2.approx.f32 %0, %1;" : "=f"(r) : "f"(x));
    return r;
}
__device__ __forceinline__ unsigned f16pack(float lo, float hi) {
    unsigned r;
    asm("cvt.rn.f16x2.f32 %0, %1, %2;" : "=r"(r) : "f"(hi), "f"(lo));
    return r;
}

#define LDSM4(r0, r1, r2, r3, addr)                                          \
    asm volatile("ldmatrix.sync.aligned.m8n8.x4.shared.b16 {%0,%1,%2,%3}, [%4];" \
                 : "=r"(r0), "=r"(r1), "=r"(r2), "=r"(r3) : "r"(addr))

#define MMA(d, a, b)                                                         \
    asm volatile("mma.sync.aligned.m16n8k16.row.col.f32.f16.f16.f32 "        \
                 "{%0,%1,%2,%3},{%4,%5,%6,%7},{%8,%9},{%0,%1,%2,%3};"        \
                 : "+f"((d)[0]), "+f"((d)[1]), "+f"((d)[2]), "+f"((d)[3])    \
                 : "r"((a)[0]), "r"((a)[1]), "r"((a)[2]), "r"((a)[3]),       \
                   "r"((b)[0]), "r"((b)[1]))

#define CP16(dst, src) \
    asm volatile("cp.async.cg.shared.global [%0], [%1], 16;" :: "r"(dst), "l"(src))
#define CP_COMMIT() asm volatile("cp.async.commit_group;" ::: "memory")
#define CP_WAIT0()  asm volatile("cp.async.wait_group 0;" ::: "memory")

// ---------------------------------------------------------------------------
// Device scratch
// ---------------------------------------------------------------------------
__device__ __align__(16) __half g_emb[NROWS * PP];
__device__ __align__(16) __half g_wt[PP * HH];   // [n][k] K-major
__device__ float g_partial[BB * 8];
__device__ int2 g_counts[BB];
__device__ int g_done = 0;

// ---------------------------------------------------------------------------
// Kernel 0: W -> fp16 transposed to [n][k] via smem transpose (coalesced).
// Grid 10 blocks x (128k x 128n).
// ---------------------------------------------------------------------------
__global__ __launch_bounds__(256) void kern_wt(const float* __restrict__ W) {
    __shared__ unsigned short smT[128 * 136];   // [k][n], pad 8
    const int tid = threadIdx.x;
    const int k0 = blockIdx.x * 128;
    // load + convert: each thread 16 float4 (coalesced)
#pragma unroll
    for (int i = 0; i < 16; i++) {
        int u = i * 256 + tid;                 // 0..4095
        int row = u >> 5, c4 = u & 31;         // row=k, c4*4=n
        float4 v = *(const float4*)(W + (size_t)(k0 + row) * PP + c4 * 4);
        unsigned h01 = f16pack(v.x, v.y);
        unsigned h23 = f16pack(v.z, v.w);
        *(unsigned*)&smT[row * 136 + c4 * 4] = h01;
        *(unsigned*)&smT[row * 136 + c4 * 4 + 2] = h23;
    }
    __syncthreads();
    // write transposed: thread handles (n, kq): 8 halves along k -> uint4
#pragma unroll
    for (int i = 0; i < 8; i++) {
        int u = i * 256 + tid;                 // 0..2047
        int kq = u >> 4, n = u & 15;           // kq: 0..127 (8-k groups? no: kq 0..127)
        // remap: 128 n x 16 kq-groups
        int nn = (u >> 4) & 127;               // n row 0..127
        int kg = (u & 15);                     // k-group 0..15
        unsigned short h[8];
#pragma unroll
        for (int j = 0; j < 8; j++) h[j] = smT[(kg * 8 + j) * 136 + nn];
        uint4 o;
        o.x = (unsigned)h[0] | ((unsigned)h[1] << 16);
        o.y = (unsigned)h[2] | ((unsigned)h[3] << 16);
        o.z = (unsigned)h[4] | ((unsigned)h[5] << 16);
        o.w = (unsigned)h[6] | ((unsigned)h[7] << 16);
        *(uint4*)(g_wt + (size_t)nn * HH + k0 + kg * 8) = o;
        (void)kq; (void)n;
    }
}

__global__ void kern_nop() {}

// ---------------------------------------------------------------------------
// Kernel 1: proj + L2-normalize; invalid rows stored as ZERO.
// M=128/CTA, A+B double-buffered, 1 sync/chunk, XOR-hoisted ldsm addresses.
// ---------------------------------------------------------------------------
#define P_A(b) (2048 + (b) * 16384)
#define P_B(b) (34816 + (b) * 16384)
#define PROJ_SMEM 67584

__global__ __launch_bounds__(256, 2)
void kern_proj(const float* __restrict__ hid, const float* __restrict__ bias,
               const int* __restrict__ amask, const int* __restrict__ labels) {
    extern __shared__ char sm[];
    const unsigned sb = smem_to_u32(sm);
    const int tid = threadIdx.x, lane = tid & 31, wid = tid >> 5;
    const int wm = wid & 3, wn = wid >> 2;
    const int m0 = wm * 32, n0 = wn * 64;
    const int row0 = blockIdx.x * 128;
    float* bias_s = (float*)sm;
    float* ssbuf = (float*)(sm + 512);

    if (tid < 128) bias_s[tid] = bias[tid];

    // hoisted swizzle bases (offsets within tile)
    unsigned swxA[2], swxB[4];
#pragma unroll
    for (int mt = 0; mt < 2; mt++) {
        unsigned r = m0 + mt * 16 + (lane & 15);
        swxA[mt] = sw128(r * 128 + ((lane >> 4) << 4));
    }
    {
        unsigned q = lane >> 3;
#pragma unroll
        for (int p = 0; p < 4; p++) {
            unsigned nr = n0 + p * 16 + ((q >> 1) << 3) + (lane & 7);
            swxB[p] = sw128(nr * 128 + ((q & 1) << 4));
        }
    }

    float acc[2][8][4];
#pragma unroll
    for (int mt = 0; mt < 2; mt++)
#pragma unroll
        for (int nt = 0; nt < 8; nt++)
#pragma unroll
            for (int e = 0; e < 4; e++) acc[mt][nt][e] = 0.f;

#pragma unroll
    for (int i = 0; i < 4; i++) {
        int u = i * 256 + tid;
        int n = u >> 3, k8 = u & 7;
        CP16(sb + P_B(0) + sw128((unsigned)(n * 128 + k8 * 16)),
             g_wt + (size_t)n * HH + k8 * 8);
    }
    CP_COMMIT();
#pragma unroll
    for (int q = 0; q < 4; q++) {
        int u = q * 256 + tid;
        int row = u >> 3, k8 = u & 7;
        const float* s = hid + (size_t)(row0 + row) * HH + k8 * 8;
        float4 v0 = *(const float4*)s;
        float4 v1 = *(const float4*)(s + 4);
        uint4 ra = make_uint4(f16pack(v0.x, v0.y), f16pack(v0.z, v0.w),
                              f16pack(v1.x, v1.y), f16pack(v1.z, v1.w));
        *(uint4*)(sm + P_A(0) + sw128((unsigned)(row * 128 + k8 * 16))) = ra;
    }
    CP_WAIT0();
    __syncthreads();

#pragma unroll 1
    for (int c = 0; c < 20; c++) {
        const int buf = c & 1;
        float4 va[8];
        if (c < 19) {
            const int k0n = (c + 1) * 64;
#pragma unroll
            for (int q = 0; q < 4; q++) {
                int u = q * 256 + tid;
                int row = u >> 3, k8 = u & 7;
                const float* s = hid + (size_t)(row0 + row) * HH + k0n + k8 * 8;
                va[2 * q] = *(const float4*)s;
                va[2 * q + 1] = *(const float4*)(s + 4);
            }
#pragma unroll
            for (int i = 0; i < 4; i++) {
                int u = i * 256 + tid;
                int n = u >> 3, k8 = u & 7;
                CP16(sb + P_B(buf ^ 1) + sw128((unsigned)(n * 128 + k8 * 16)),
                     g_wt + (size_t)n * HH + k0n + k8 * 8);
            }
            CP_COMMIT();
        }

        const unsigned a_base = sb + P_A(buf);
        const unsigned b_base = sb + P_B(buf);
#pragma unroll
        for (int kk = 0; kk < 4; kk++) {
            const unsigned kk2 = kk * 32;
            unsigned ah[2][4], bh[8][2];
#pragma unroll
            for (int mt = 0; mt < 2; mt++)
                LDSM4(ah[mt][0], ah[mt][1], ah[mt][2], ah[mt][3],
                      a_base + (swxA[mt] ^ kk2));
#pragma unroll
            for (int p = 0; p < 4; p++) {
                unsigned t0, t1, t2, t3;
                LDSM4(t0, t1, t2, t3, b_base + (swxB[p] ^ kk2));
                bh[2 * p][0] = t0; bh[2 * p][1] = t1;
                bh[2 * p + 1][0] = t2; bh[2 * p + 1][1] = t3;
            }
#pragma unroll
            for (int mt = 0; mt < 2; mt++)
#pragma unroll
                for (int nt = 0; nt < 8; nt++)
                    MMA(acc[mt][nt], ah[mt], bh[nt]);
        }

        if (c < 19) {
#pragma unroll
            for (int q = 0; q < 4; q++) {
                int u = q * 256 + tid;
                int row = u >> 3, k8 = u & 7;
                uint4 ra = make_uint4(
                    f16pack(va[2 * q].x, va[2 * q].y),
                    f16pack(va[2 * q].z, va[2 * q].w),
                    f16pack(va[2 * q + 1].x, va[2 * q + 1].y),
                    f16pack(va[2 * q + 1].z, va[2 * q + 1].w));
                *(uint4*)(sm + P_A(buf ^ 1) + sw128((unsigned)(row * 128 + k8 * 16))) = ra;
            }
            CP_WAIT0();
        }
        __syncthreads();
    }

    // epilogue: bias, L2 norm, ZERO invalid rows, store fp16 emb
    float ss[4] = {0.f, 0.f, 0.f, 0.f};
#pragma unroll
    for (int mt = 0; mt < 2; mt++)
#pragma unroll
        for (int nt = 0; nt < 8; nt++)
#pragma unroll
            for (int e = 0; e < 4; e++) {
                int s = e >> 1;
                int col = n0 + nt * 8 + (lane & 3) * 2 + (e & 1);
                float v = acc[mt][nt][e] + bias_s[col];
                acc[mt][nt][e] = v;
                ss[mt * 2 + s] += v * v;
            }
#pragma unroll
    for (int r2 = 0; r2 < 4; r2++) {
        ss[r2] += __shfl_xor_sync(0xffffffffu, ss[r2], 1);
        ss[r2] += __shfl_xor_sync(0xffffffffu, ss[r2], 2);
    }
    if ((lane & 3) == 0) {
#pragma unroll
        for (int r2 = 0; r2 < 4; r2++) {
            int rowg = wm * 32 + (r2 >> 1) * 16 + (lane >> 2) + (r2 & 1) * 8;
            ssbuf[wn * 128 + rowg] = ss[r2];
        }
    }
    __syncthreads();
#pragma unroll
    for (int r2 = 0; r2 < 4; r2++) {
        int mt = r2 >> 1, s = r2 & 1;
        int rowg = wm * 32 + mt * 16 + (lane >> 2) + s * 8;
        int gr = row0 + rowg;
        int vv = (amask[gr] != 0) && (labels[gr] != -100);
        float tot = ssbuf[rowg] + ssbuf[128 + rowg];
        float inv = rsqrtf(tot);
        inv = inv * (1.5f - 0.5f * tot * inv * inv);
        if (!vv) inv = 0.f;
        __half* oh = g_emb + (size_t)gr * PP;
#pragma unroll
        for (int nt = 0; nt < 8; nt++) {
            int col = n0 + nt * 8 + (lane & 3) * 2;
            *(unsigned*)(oh + col) =
                f16pack(acc[mt][nt][s * 2] * inv, acc[mt][nt][s * 2 + 1] * inv);
        }
    }
}

// ---------------------------------------------------------------------------
// Kernel 2: sim-HMMA + contrastive stats. CTA = M128 x N64, 8 warps m32n32
// (4m x 2n), grid 256, occ 3 single wave. Maskless se + correction, popc np,
// B double-buffered, XOR-hoisted addresses, last-CTA final reduction.
// ---------------------------------------------------------------------------
#define SM2_WPART 0
#define SM2_MASK  64
#define SM2_CNT   192
#define SM2_RED   256
#define SM2_A     4608
#define SM2_B(b)  (37376 + (b) * 16384)
#define SIM_SMEM  70144

__global__ __launch_bounds__(256, 3)
void kern_sim(const int* __restrict__ amask, const int* __restrict__ labels,
              float* __restrict__ out) {
    extern __shared__ char sm[];
    __shared__ int lastf;
    const unsigned sb = smem_to_u32(sm);
    const int tid = threadIdx.x, lane = tid & 31, wid = tid >> 5;
    const int wm = wid & 3, wn = wid >> 2;     // 4 m-warps x 2 n-warps
    const int m0 = wm * 32, n0 = wn * 32;
    const int b = blockIdx.x >> 3, it = blockIdx.x & 7;
    const int i0 = it * 128;
    const __half* eb = g_emb + (size_t)b * LL * PP;
    float* wpart = (float*)(sm + SM2_WPART);
    unsigned* valm = (unsigned*)(sm + SM2_MASK);    // [parity*2 + word]
    unsigned* posm = valm + 4;                      // [parity*8 + l*2 + word]
    int* cnt = (int*)(sm + SM2_CNT);
    const int sh = (lane & 3) * 2;
    const unsigned mthr = (0x3u << sh) * 0x01010101u;

    // hoisted swizzle bases
    unsigned swxA[2], swxB[2];
#pragma unroll
    for (int mt = 0; mt < 2; mt++) {
        unsigned r = m0 + mt * 16 + (lane & 15);
        swxA[mt] = sw128(r * 128 + ((lane >> 4) << 4));
    }
    {
        unsigned q = lane >> 3;
#pragma unroll
        for (int p = 0; p < 2; p++) {
            unsigned nr = n0 + p * 16 + ((q >> 1) << 3) + (lane & 7);
            swxB[p] = sw128(nr * 128 + ((q & 1) << 4));
        }
    }

    // A tile (128 rows x 128k = 32KB): 8 CP16/thread
#pragma unroll
    for (int i = 0; i < 8; i++) {
        int u = i * 256 + tid;
        int row = u >> 4, k8 = u & 15;
        unsigned off = (unsigned)((k8 >> 3) * 16384) +
                       sw128((unsigned)(row * 128 + (k8 & 7) * 16));
        CP16(sb + SM2_A + off, eb + (size_t)(i0 + row) * PP + k8 * 8);
    }
    // B tile 0 (64 rows = 16KB): 4 CP16/thread
#pragma unroll
    for (int i = 0; i < 4; i++) {
        int u = i * 256 + tid;
        int row = u >> 4, k8 = u & 15;
        unsigned off = (unsigned)((k8 >> 3) * 8192) +
                       sw128((unsigned)(row * 128 + (k8 & 7) * 16));
        CP16(sb + SM2_B(0) + off, eb + (size_t)row * PP + k8 * 8);
    }
    CP_COMMIT();

    int labi_[4], np_[4];
    float se_[4], sp_[4];
#pragma unroll
    for (int r2 = 0; r2 < 4; r2++) {
        int rowg = wm * 32 + (r2 >> 1) * 16 + (lane >> 2) + (r2 & 1) * 8;
        int gi = i0 + rowg;
        int lb = labels[b * LL + gi];
        labi_[r2] = ((amask[b * LL + gi] != 0) && (lb != -100)) ? lb : -1;
        se_[r2] = 0.f; sp_[r2] = 0.f; np_[r2] = 0;
    }
    int nv = 0;

#pragma unroll 1
    for (int jt = 0; jt < 16; jt++) {
        const int buf = jt & 1;
        const int par = jt & 1;
        const int j0 = jt * 64;
        if (tid < 64) {
            int mm = amask[b * LL + j0 + tid];
            int lb = labels[b * LL + j0 + tid];
            int vv = (mm != 0) && (lb != -100);
            unsigned vmb = __ballot_sync(0xffffffffu, vv);
            if (lane == 0) valm[par * 2 + wid] = vmb;
#pragma unroll
            for (int l = 0; l < 4; l++) {
                unsigned pb = __ballot_sync(0xffffffffu, vv && (lb == l));
                if (lane == 0) posm[par * 8 + l * 2 + wid] = pb;
            }
        }
        CP_WAIT0();
        __syncthreads();
        nv += __popc(valm[par * 2]) + __popc(valm[par * 2 + 1]);

        float acc[2][4][4];
#pragma unroll
        for (int mt = 0; mt < 2; mt++)
#pragma unroll
            for (int nt = 0; nt < 4; nt++)
#pragma unroll
                for (int e = 0; e < 4; e++) acc[mt][nt][e] = 0.f;

        const unsigned aT = sb + SM2_A;
        const unsigned bT = sb + SM2_B(buf);
#pragma unroll
        for (int kk = 0; kk < 8; kk++) {
            const unsigned chA = (unsigned)((kk >> 2) * 16384);
            const unsigned chB = (unsigned)((kk >> 2) * 8192);
            const unsigned kk2 = (kk & 3) * 32;
            unsigned ah[2][4], bh[4][2];
#pragma unroll
            for (int mt = 0; mt < 2; mt++)
                LDSM4(ah[mt][0], ah[mt][1], ah[mt][2], ah[mt][3],
                      aT + chA + (swxA[mt] ^ kk2));
#pragma unroll
            for (int p = 0; p < 2; p++) {
                unsigned t0, t1, t2, t3;
                LDSM4(t0, t1, t2, t3, bT + chB + (swxB[p] ^ kk2));
                bh[2 * p][0] = t0; bh[2 * p][1] = t1;
                bh[2 * p + 1][0] = t2; bh[2 * p + 1][1] = t3;
            }
#pragma unroll
            for (int mt = 0; mt < 2; mt++)
#pragma unroll
                for (int nt = 0; nt < 4; nt++)
                    MMA(acc[mt][nt], ah[mt], bh[nt]);
        }

        // issue next B tile (overlaps epilogue)
        if (jt < 15) {
            const int j0n = j0 + 64;
#pragma unroll
            for (int i = 0; i < 4; i++) {
                int u = i * 256 + tid;
                int row = u >> 4, k8 = u & 15;
                unsigned off = (unsigned)((k8 >> 3) * 8192) +
                               sw128((unsigned)(row * 128 + (k8 & 7) * 16));
                CP16(sb + SM2_B(buf ^ 1) + off, eb + (size_t)(j0n + row) * PP + k8 * 8);
            }
            CP_COMMIT();
        }

        // epilogue: maskless se; sp via pos bits; np via popc
#pragma unroll
        for (int r2 = 0; r2 < 4; r2++) {
            int mt = r2 >> 1, s = r2 & 1;
            int rowg = wm * 32 + mt * 16 + (lane >> 2) + s * 8;
            unsigned pmr = (labi_[r2] >= 0)
                               ? posm[par * 8 + labi_[r2] * 2 + wn] : 0u;
            float se = se_[r2], sp = sp_[r2];
            int np = np_[r2];
            // diagonal tile for this row: jt == it*2 + (rowg>>6), word == wn
            if ((jt == it * 2 + (rowg >> 6)) && (((rowg >> 5) & 1) == wn)) {
                int dbp = rowg & 31;
                pmr &= ~(1u << dbp);
                np += __popc(pmr & mthr);
#pragma unroll
                for (int nt = 0; nt < 4; nt++)
#pragma unroll
                    for (int cc = 0; cc < 2; cc++) {
                        int bp = nt * 8 + sh + cc;
                        float a = acc[mt][nt][s * 2 + cc];
                        float e = ex2f(fmaf(a, C1F, -C1F));
                        se += (bp == dbp) ? 0.f : e;
                        if ((pmr >> bp) & 1) sp += a;
                    }
            } else {
                np += __popc(pmr & mthr);
#pragma unroll
                for (int nt = 0; nt < 4; nt++)
#pragma unroll
                    for (int cc = 0; cc < 2; cc++) {
                        int bp = nt * 8 + sh + cc;
                        float a = acc[mt][nt][s * 2 + cc];
                        se += ex2f(fmaf(a, C1F, -C1F));
                        if ((pmr >> bp) & 1) sp += a;
                    }
            }
            se_[r2] = se; sp_[r2] = sp; np_[r2] = np;
        }
    }

    // per-batch counts (it==0 CTAs)
    if (it == 0) {
        int cm = 0, cv = 0;
#pragma unroll
        for (int q = 0; q < 4; q++) {
            int row = q * 256 + tid;
            int mm = amask[b * LL + row];
            int lb = labels[b * LL + row];
            cm += (mm != 0);
            cv += (mm != 0) && (lb != -100);
        }
#pragma unroll
        for (int o = 16; o >= 1; o >>= 1) {
            cm += __shfl_xor_sync(0xffffffffu, cm, o);
            cv += __shfl_xor_sync(0xffffffffu, cv, o);
        }
        if (lane == 0) { cnt[wid * 2] = cm; cnt[wid * 2 + 1] = cv; }
    }

    // merge: 4 lanes/row, then 2 wn groups via smem
#pragma unroll
    for (int o = 1; o <= 2; o <<= 1)
#pragma unroll
        for (int r2 = 0; r2 < 4; r2++) {
            se_[r2] += __shfl_xor_sync(0xffffffffu, se_[r2], o);
            sp_[r2] += __shfl_xor_sync(0xffffffffu, sp_[r2], o);
            np_[r2] += __shfl_xor_sync(0xffffffffu, np_[r2], o);
        }
    __syncthreads();
    if ((lane & 3) == 0) {
#pragma unroll
        for (int r2 = 0; r2 < 4; r2++) {
            int rowg = wm * 32 + (r2 >> 1) * 16 + (lane >> 2) + (r2 & 1) * 8;
            *(float4*)(sm + SM2_RED + (wn * 128 + rowg) * 16) =
                make_float4(se_[r2], sp_[r2], (float)np_[r2], 0.f);
        }
    }
    __syncthreads();
    float alsum = 0.f;
    if (wn == 0 && (lane & 3) == 0) {
        const float corrE = ex2f(-C1F);
        const float n_inv = (float)(LL - nv);
#pragma unroll
        for (int r2 = 0; r2 < 4; r2++) {
            int rowg = wm * 32 + (r2 >> 1) * 16 + (lane >> 2) + (r2 & 1) * 8;
            float4 q0 = *(const float4*)(sm + SM2_RED + rowg * 16);
            float4 q1 = *(const float4*)(sm + SM2_RED + (128 + rowg) * 16);
            float se = q0.x + q1.x, sp = q0.y + q1.y, np = q0.z + q1.z;
            float sec = se - n_inv * corrE;
            alsum += (INVT * sp - np * (INVT + __logf(sec + 1e-12f))) / (np + 1e-12f);
        }
    }
    if (wn == 0) {
#pragma unroll
        for (int o = 16; o >= 1; o >>= 1)
            alsum += __shfl_xor_sync(0xffffffffu, alsum, o);
        if (lane == 0) wpart[wid] = alsum;
    }
    __syncthreads();
    if (tid == 0) {
        g_partial[blockIdx.x] = wpart[0] + wpart[1] + wpart[2] + wpart[3];
        if (it == 0) {
            int tm = 0, tv = 0;
#pragma unroll
            for (int w = 0; w < 8; w++) { tm += cnt[w * 2]; tv += cnt[w * 2 + 1]; }
            g_counts[b] = make_int2(tm, tv);
        }
    }

    // last-CTA deterministic final reduction
    __threadfence();
    if (tid == 0) {
        int t = atomicAdd(&g_done, 1);
        lastf = (t == BB * 8 - 1);
    }
    __syncthreads();
    if (lastf) {
        __threadfence();
        if (tid < 32) {
            float ps = 0.f;
#pragma unroll
            for (int t = 0; t < 8; t++) ps += __ldcg(&g_partial[tid * 8 + t]);
            int2 c;
            c.x = __ldcg(&((const int*)g_counts)[tid * 2]);
            c.y = __ldcg(&((const int*)g_counts)[tid * 2 + 1]);
            int ok = (c.x >= 2);
            float nvv = (float)(c.y >= 1 ? c.y : 1);
            float lossb = ok ? (-ps / nvv) : 0.f;
            int ns = ok;
#pragma unroll
            for (int o = 16; o >= 1; o >>= 1) {
                lossb += __shfl_xor_sync(0xffffffffu, lossb, o);
                ns += __shfl_xor_sync(0xffffffffu, ns, o);
            }
            if (tid == 0) {
                out[0] = lossb / (float)(ns > 0 ? ns : 1);
                g_done = 0;
            }
        }
    }
}

// ---------------------------------------------------------------------------
extern "C" void kernel_launch(void* const* d_in, const int* in_sizes, int n_in,
                              void* d_out, int out_size) {
    const float* hid = (const float*)d_in[0];
    const float* W = (const float*)d_in[1];
    const float* bias = (const float*)d_in[2];
    const int* amask = (const int*)d_in[3];
    const int* labels = (const int*)d_in[4];
    float* out = (float*)d_out;

    cudaFuncSetAttribute(kern_proj, cudaFuncAttributeMaxDynamicSharedMemorySize, PROJ_SMEM);
    cudaFuncSetAttribute(kern_sim, cudaFuncAttributeMaxDynamicSharedMemorySize, SIM_SMEM);

    kern_wt<<<HH / 128, 256>>>(W);                                     // 0
    kern_proj<<<NROWS / 128, 256, PROJ_SMEM>>>(hid, bias, amask, labels); // 1
    kern_nop<<<1, 32>>>();                                             // 2
    kern_sim<<<BB * 8, 256, SIM_SMEM>>>(amask, labels, out);           // 3 (ncu)
}

// round 14
// speedup vs baseline: 1.4428x; 1.0534x over previous
#include <cuda_runtime.h>
#include <cuda_fp16.h>

#define BB 32
#define LL 1024
#define HH 1280
#define PP 128
#define NROWS (BB * LL)
#define INVT 14.285714285714286f
#define C1F (14.285714285714286f * 1.4426950408889634f)

// ---------------------------------------------------------------------------
// Helpers
// ---------------------------------------------------------------------------
__device__ __forceinline__ unsigned smem_to_u32(const void* p) {
    unsigned a;
    asm("{ .reg .u64 t; cvta.to.shared.u64 t, %1; cvt.u32.u64 %0, t; }" : "=r"(a) : "l"(p));
    return a;
}
static __device__ __forceinline__ unsigned sw128(unsigned off) {
    return off ^ ((off >> 3) & 0x70);
}
__device__ __forceinline__ float ex2f(float x) {
    float r;
    asm("ex2.approx.f32 %0, %1;" : "=f"(r) : "f"(x));
    return r;
}
__device__ __forceinline__ unsigned f16pack(float lo, float hi) {
    unsigned r;
    asm("cvt.rn.f16x2.f32 %0, %1, %2;" : "=r"(r) : "f"(hi), "f"(lo));
    return r;
}

#define LDSM4(r0, r1, r2, r3, addr)                                          \
    asm volatile("ldmatrix.sync.aligned.m8n8.x4.shared.b16 {%0,%1,%2,%3}, [%4];" \
                 : "=r"(r0), "=r"(r1), "=r"(r2), "=r"(r3) : "r"(addr))

#define MMA(d, a, b)                                                         \
    asm volatile("mma.sync.aligned.m16n8k16.row.col.f32.f16.f16.f32 "        \
                 "{%0,%1,%2,%3},{%4,%5,%6,%7},{%8,%9},{%0,%1,%2,%3};"        \
                 : "+f"((d)[0]), "+f"((d)[1]), "+f"((d)[2]), "+f"((d)[3])    \
                 : "r"((a)[0]), "r"((a)[1]), "r"((a)[2]), "r"((a)[3]),       \
                   "r"((b)[0]), "r"((b)[1]))

#define CP16(dst, src) \
    asm volatile("cp.async.cg.shared.global [%0], [%1], 16;" :: "r"(dst), "l"(src))
#define CP_COMMIT() asm volatile("cp.async.commit_group;" ::: "memory")
#define CP_WAIT0()  asm volatile("cp.async.wait_group 0;" ::: "memory")

// ---------------------------------------------------------------------------
// Device scratch
// ---------------------------------------------------------------------------
__device__ __align__(16) __half g_emb[NROWS * PP];
__device__ __align__(16) __half g_wt[PP * HH];   // [n][k] K-major
__device__ __align__(16) float g_se[NROWS];
__device__ __align__(16) float g_sp[NROWS];
__device__ int g_cnt4[BB * 4];
__device__ int g_cm[BB];
__device__ int g_cv[BB];
__device__ float g_partial[BB * 8];
__device__ int g_done = 0;

// ---------------------------------------------------------------------------
// Kernel 0: blocks 0..9: W -> fp16 [n][k] via smem transpose.
//           blocks 10..73: zero g_se/g_sp. block 74: zero count arrays.
// ---------------------------------------------------------------------------
__global__ __launch_bounds__(256) void kern_wt(const float* __restrict__ W) {
    const int tid = threadIdx.x;
    if (blockIdx.x >= 10) {
        if (blockIdx.x < 74) {
            int idx = (blockIdx.x - 10) * 1024 + tid * 4;   // [0, 65536)
            float4 z = make_float4(0.f, 0.f, 0.f, 0.f);
            if (idx < NROWS) *(float4*)(g_se + idx) = z;
            else             *(float4*)(g_sp + idx - NROWS) = z;
        } else {
            if (tid < 128) g_cnt4[tid] = 0;
            else if (tid < 160) g_cm[tid - 128] = 0;
            else if (tid < 192) g_cv[tid - 160] = 0;
        }
        return;
    }
    __shared__ unsigned short smT[128 * 136];
    const int k0 = blockIdx.x * 128;
#pragma unroll
    for (int i = 0; i < 16; i++) {
        int u = i * 256 + tid;
        int row = u >> 5, c4 = u & 31;
        float4 v = *(const float4*)(W + (size_t)(k0 + row) * PP + c4 * 4);
        *(unsigned*)&smT[row * 136 + c4 * 4] = f16pack(v.x, v.y);
        *(unsigned*)&smT[row * 136 + c4 * 4 + 2] = f16pack(v.z, v.w);
    }
    __syncthreads();
#pragma unroll
    for (int i = 0; i < 8; i++) {
        int u = i * 256 + tid;
        int nn = (u >> 4) & 127;
        int kg = (u & 15);
        unsigned short h[8];
#pragma unroll
        for (int j = 0; j < 8; j++) h[j] = smT[(kg * 8 + j) * 136 + nn];
        uint4 o;
        o.x = (unsigned)h[0] | ((unsigned)h[1] << 16);
        o.y = (unsigned)h[2] | ((unsigned)h[3] << 16);
        o.z = (unsigned)h[4] | ((unsigned)h[5] << 16);
        o.w = (unsigned)h[6] | ((unsigned)h[7] << 16);
        *(uint4*)(g_wt + (size_t)nn * HH + k0 + kg * 8) = o;
    }
}

// ---------------------------------------------------------------------------
// Kernel 1: proj + L2-normalize; invalid rows stored as ZERO (R13, unchanged)
// ---------------------------------------------------------------------------
#define P_A(b) (2048 + (b) * 16384)
#define P_B(b) (34816 + (b) * 16384)
#define PROJ_SMEM 67584

__global__ __launch_bounds__(256, 2)
void kern_proj(const float* __restrict__ hid, const float* __restrict__ bias,
               const int* __restrict__ amask, const int* __restrict__ labels) {
    extern __shared__ char sm[];
    const unsigned sb = smem_to_u32(sm);
    const int tid = threadIdx.x, lane = tid & 31, wid = tid >> 5;
    const int wm = wid & 3, wn = wid >> 2;
    const int m0 = wm * 32, n0 = wn * 64;
    const int row0 = blockIdx.x * 128;
    float* bias_s = (float*)sm;
    float* ssbuf = (float*)(sm + 512);

    if (tid < 128) bias_s[tid] = bias[tid];

    unsigned swxA[2], swxB[4];
#pragma unroll
    for (int mt = 0; mt < 2; mt++) {
        unsigned r = m0 + mt * 16 + (lane & 15);
        swxA[mt] = sw128(r * 128 + ((lane >> 4) << 4));
    }
    {
        unsigned q = lane >> 3;
#pragma unroll
        for (int p = 0; p < 4; p++) {
            unsigned nr = n0 + p * 16 + ((q >> 1) << 3) + (lane & 7);
            swxB[p] = sw128(nr * 128 + ((q & 1) << 4));
        }
    }

    float acc[2][8][4];
#pragma unroll
    for (int mt = 0; mt < 2; mt++)
#pragma unroll
        for (int nt = 0; nt < 8; nt++)
#pragma unroll
            for (int e = 0; e < 4; e++) acc[mt][nt][e] = 0.f;

#pragma unroll
    for (int i = 0; i < 4; i++) {
        int u = i * 256 + tid;
        int n = u >> 3, k8 = u & 7;
        CP16(sb + P_B(0) + sw128((unsigned)(n * 128 + k8 * 16)),
             g_wt + (size_t)n * HH + k8 * 8);
    }
    CP_COMMIT();
#pragma unroll
    for (int q = 0; q < 4; q++) {
        int u = q * 256 + tid;
        int row = u >> 3, k8 = u & 7;
        const float* s = hid + (size_t)(row0 + row) * HH + k8 * 8;
        float4 v0 = *(const float4*)s;
        float4 v1 = *(const float4*)(s + 4);
        uint4 ra = make_uint4(f16pack(v0.x, v0.y), f16pack(v0.z, v0.w),
                              f16pack(v1.x, v1.y), f16pack(v1.z, v1.w));
        *(uint4*)(sm + P_A(0) + sw128((unsigned)(row * 128 + k8 * 16))) = ra;
    }
    CP_WAIT0();
    __syncthreads();

#pragma unroll 1
    for (int c = 0; c < 20; c++) {
        const int buf = c & 1;
        float4 va[8];
        if (c < 19) {
            const int k0n = (c + 1) * 64;
#pragma unroll
            for (int q = 0; q < 4; q++) {
                int u = q * 256 + tid;
                int row = u >> 3, k8 = u & 7;
                const float* s = hid + (size_t)(row0 + row) * HH + k0n + k8 * 8;
                va[2 * q] = *(const float4*)s;
                va[2 * q + 1] = *(const float4*)(s + 4);
            }
#pragma unroll
            for (int i = 0; i < 4; i++) {
                int u = i * 256 + tid;
                int n = u >> 3, k8 = u & 7;
                CP16(sb + P_B(buf ^ 1) + sw128((unsigned)(n * 128 + k8 * 16)),
                     g_wt + (size_t)n * HH + k0n + k8 * 8);
            }
            CP_COMMIT();
        }

        const unsigned a_base = sb + P_A(buf);
        const unsigned b_base = sb + P_B(buf);
#pragma unroll
        for (int kk = 0; kk < 4; kk++) {
            const unsigned kk2 = kk * 32;
            unsigned ah[2][4], bh[8][2];
#pragma unroll
            for (int mt = 0; mt < 2; mt++)
                LDSM4(ah[mt][0], ah[mt][1], ah[mt][2], ah[mt][3],
                      a_base + (swxA[mt] ^ kk2));
#pragma unroll
            for (int p = 0; p < 4; p++) {
                unsigned t0, t1, t2, t3;
                LDSM4(t0, t1, t2, t3, b_base + (swxB[p] ^ kk2));
                bh[2 * p][0] = t0; bh[2 * p][1] = t1;
                bh[2 * p + 1][0] = t2; bh[2 * p + 1][1] = t3;
            }
#pragma unroll
            for (int mt = 0; mt < 2; mt++)
#pragma unroll
                for (int nt = 0; nt < 8; nt++)
                    MMA(acc[mt][nt], ah[mt], bh[nt]);
        }

        if (c < 19) {
#pragma unroll
            for (int q = 0; q < 4; q++) {
                int u = q * 256 + tid;
                int row = u >> 3, k8 = u & 7;
                uint4 ra = make_uint4(
                    f16pack(va[2 * q].x, va[2 * q].y),
                    f16pack(va[2 * q].z, va[2 * q].w),
                    f16pack(va[2 * q + 1].x, va[2 * q + 1].y),
                    f16pack(va[2 * q + 1].z, va[2 * q + 1].w));
                *(uint4*)(sm + P_A(buf ^ 1) + sw128((unsigned)(row * 128 + k8 * 16))) = ra;
            }
            CP_WAIT0();
        }
        __syncthreads();
    }

    float ss[4] = {0.f, 0.f, 0.f, 0.f};
#pragma unroll
    for (int mt = 0; mt < 2; mt++)
#pragma unroll
        for (int nt = 0; nt < 8; nt++)
#pragma unroll
            for (int e = 0; e < 4; e++) {
                int s = e >> 1;
                int col = n0 + nt * 8 + (lane & 3) * 2 + (e & 1);
                float v = acc[mt][nt][e] + bias_s[col];
                acc[mt][nt][e] = v;
                ss[mt * 2 + s] += v * v;
            }
#pragma unroll
    for (int r2 = 0; r2 < 4; r2++) {
        ss[r2] += __shfl_xor_sync(0xffffffffu, ss[r2], 1);
        ss[r2] += __shfl_xor_sync(0xffffffffu, ss[r2], 2);
    }
    if ((lane & 3) == 0) {
#pragma unroll
        for (int r2 = 0; r2 < 4; r2++) {
            int rowg = wm * 32 + (r2 >> 1) * 16 + (lane >> 2) + (r2 & 1) * 8;
            ssbuf[wn * 128 + rowg] = ss[r2];
        }
    }
    __syncthreads();
#pragma unroll
    for (int r2 = 0; r2 < 4; r2++) {
        int mt = r2 >> 1, s = r2 & 1;
        int rowg = wm * 32 + mt * 16 + (lane >> 2) + s * 8;
        int gr = row0 + rowg;
        int vv = (amask[gr] != 0) && (labels[gr] != -100);
        float tot = ssbuf[rowg] + ssbuf[128 + rowg];
        float inv = rsqrtf(tot);
        inv = inv * (1.5f - 0.5f * tot * inv * inv);
        if (!vv) inv = 0.f;
        __half* oh = g_emb + (size_t)gr * PP;
#pragma unroll
        for (int nt = 0; nt < 8; nt++) {
            int col = n0 + nt * 8 + (lane & 3) * 2;
            *(unsigned*)(oh + col) =
                f16pack(acc[mt][nt][s * 2] * inv, acc[mt][nt][s * 2 + 1] * inv);
        }
    }
}

// ---------------------------------------------------------------------------
// Kernel 2: SYMMETRIC sim. Grid 32 x 36 upper-tri (it,jt) 128x128 blocks.
// 512 threads, 16 warps (4m x 4n, m32n32). Off-diag blocks produce row AND
// col stats; accumulate to g_se/g_sp via atomicAdd. np -> global label counts.
// ---------------------------------------------------------------------------
#define SMS_LABJ   0
#define SMS_POSM   512
#define SMS_ROWRED 1024
#define SMS_COLRED 5120
#define SMS_A      10240
#define SMS_B      43008
#define SIM_SMEM   75776

__global__ __launch_bounds__(512)
void kern_sim(const int* __restrict__ amask, const int* __restrict__ labels) {
    extern __shared__ char sm[];
    const unsigned sb = smem_to_u32(sm);
    const int tid = threadIdx.x, lane = tid & 31, wid = tid >> 5;
    const int wm = wid & 3, wn = wid >> 2;
    const int m0 = wm * 32, n0 = wn * 32;
    const int b = blockIdx.x / 36;
    int p = blockIdx.x % 36;
    int it = 0;
    while (p >= 8 - it) { p -= 8 - it; it++; }
    const int jt = it + p;
    const int diag = (it == jt);
    const int i0 = it * 128, j0 = jt * 128;
    const __half* eb = g_emb + (size_t)b * LL * PP;
    int* labjp = (int*)sm;
    unsigned* posm = (unsigned*)(sm + SMS_POSM);
    float* rowred = (float*)(sm + SMS_ROWRED);   // [wn4][row128][2]
    float* colred = (float*)(sm + SMS_COLRED);   // [wm4][col128][2]

    // loads: A tile (rows i0..i0+128): 4 CP16/thread; B tile unless diag
#pragma unroll
    for (int i = 0; i < 4; i++) {
        int u = i * 512 + tid;
        int row = u >> 4, k8 = u & 15;
        unsigned off = (unsigned)((k8 >> 3) * 16384) +
                       sw128((unsigned)(row * 128 + (k8 & 7) * 16));
        CP16(sb + SMS_A + off, eb + (size_t)(i0 + row) * PP + k8 * 8);
    }
    if (!diag) {
#pragma unroll
        for (int i = 0; i < 4; i++) {
            int u = i * 512 + tid;
            int row = u >> 4, k8 = u & 15;
            unsigned off = (unsigned)((k8 >> 3) * 16384) +
                           sw128((unsigned)(row * 128 + (k8 & 7) * 16));
            CP16(sb + SMS_B + off, eb + (size_t)(j0 + row) * PP + k8 * 8);
        }
    }
    CP_COMMIT();

    // j-range labels, pos masks; diag CTAs also count batch stats
    if (tid < 128) {
        int mm = amask[b * LL + j0 + tid];
        int lb = labels[b * LL + j0 + tid];
        int vv = (mm != 0) && (lb != -100);
        labjp[tid] = lb;
#pragma unroll
        for (int l = 0; l < 4; l++) {
            unsigned pb = __ballot_sync(0xffffffffu, vv && (lb == l));
            if (lane == 0) {
                posm[l * 4 + wid] = pb;
                if (diag) atomicAdd(&g_cnt4[b * 4 + l], __popc(pb));
            }
        }
        if (diag) {
            unsigned mb = __ballot_sync(0xffffffffu, mm != 0);
            unsigned vb = __ballot_sync(0xffffffffu, vv);
            if (lane == 0) {
                atomicAdd(&g_cm[b], __popc(mb));
                atomicAdd(&g_cv[b], __popc(vb));
            }
        }
    }

    // anchor-row labels (sentinel -1 = invalid)
    int labi_[4];
#pragma unroll
    for (int r2 = 0; r2 < 4; r2++) {
        int rowg = m0 + (r2 >> 1) * 16 + (lane >> 2) + (r2 & 1) * 8;
        int gi = b * LL + i0 + rowg;
        int lb = labels[gi];
        labi_[r2] = ((amask[gi] != 0) && (lb != -100)) ? lb : -1;
    }

    // hoisted swizzle bases
    unsigned swxA[2], swxB[2];
#pragma unroll
    for (int mt = 0; mt < 2; mt++) {
        unsigned r = m0 + mt * 16 + (lane & 15);
        swxA[mt] = sw128(r * 128 + ((lane >> 4) << 4));
    }
    {
        unsigned q = lane >> 3;
#pragma unroll
        for (int pq = 0; pq < 2; pq++) {
            unsigned nr = n0 + pq * 16 + ((q >> 1) << 3) + (lane & 7);
            swxB[pq] = sw128(nr * 128 + ((q & 1) << 4));
        }
    }

    CP_WAIT0();
    __syncthreads();

    float acc[2][4][4];
#pragma unroll
    for (int mt = 0; mt < 2; mt++)
#pragma unroll
        for (int nt = 0; nt < 4; nt++)
#pragma unroll
            for (int e = 0; e < 4; e++) acc[mt][nt][e] = 0.f;

    const unsigned aT = sb + SMS_A;
    const unsigned bT = diag ? (sb + SMS_A) : (sb + SMS_B);
#pragma unroll
    for (int kk = 0; kk < 8; kk++) {
        const unsigned ch = (unsigned)((kk >> 2) * 16384);
        const unsigned kk2 = (kk & 3) * 32;
        unsigned ah[2][4], bh[4][2];
#pragma unroll
        for (int mt = 0; mt < 2; mt++)
            LDSM4(ah[mt][0], ah[mt][1], ah[mt][2], ah[mt][3],
                  aT + ch + (swxA[mt] ^ kk2));
#pragma unroll
        for (int pq = 0; pq < 2; pq++) {
            unsigned t0, t1, t2, t3;
            LDSM4(t0, t1, t2, t3, bT + ch + (swxB[pq] ^ kk2));
            bh[2 * pq][0] = t0; bh[2 * pq][1] = t1;
            bh[2 * pq + 1][0] = t2; bh[2 * pq + 1][1] = t3;
        }
#pragma unroll
        for (int mt = 0; mt < 2; mt++)
#pragma unroll
            for (int nt = 0; nt < 4; nt++)
                MMA(acc[mt][nt], ah[mt], bh[nt]);
    }

    // ---- epilogue ----
    const int sh = (lane & 3) * 2;
    float se_[4] = {0.f, 0.f, 0.f, 0.f}, sp_[4] = {0.f, 0.f, 0.f, 0.f};
    float colse[8], colsp[8];
    int lbjv[8];
#pragma unroll
    for (int idx = 0; idx < 8; idx++) { colse[idx] = 0.f; colsp[idx] = 0.f; }
    if (!diag) {
#pragma unroll
        for (int idx = 0; idx < 8; idx++)
            lbjv[idx] = labjp[n0 + (idx >> 1) * 8 + sh + (idx & 1)];
    }

#pragma unroll
    for (int r2 = 0; r2 < 4; r2++) {
        const int mt = r2 >> 1, s = r2 & 1;
        const int rowg = m0 + mt * 16 + (lane >> 2) + s * 8;
        const int labi = labi_[r2];
        unsigned pmr = (labi >= 0) ? posm[labi * 4 + wn] : 0u;
        if (diag) {
            const int selfhere = ((rowg >> 5) == wn);
            const int bps = rowg & 31;
            if (selfhere) pmr &= ~(1u << bps);
#pragma unroll
            for (int nt = 0; nt < 4; nt++)
#pragma unroll
                for (int cc = 0; cc < 2; cc++) {
                    int bp = nt * 8 + sh + cc;
                    float a = acc[mt][nt][s * 2 + cc];
                    float e = ex2f(fmaf(a, C1F, -C1F));
                    if (selfhere && bp == bps) e = 0.f;
                    se_[r2] += e;
                    if ((pmr >> bp) & 1) sp_[r2] += a;
                }
        } else {
#pragma unroll
            for (int nt = 0; nt < 4; nt++)
#pragma unroll
                for (int cc = 0; cc < 2; cc++) {
                    int idx = nt * 2 + cc;
                    int bp = nt * 8 + sh + cc;
                    float a = acc[mt][nt][s * 2 + cc];
                    float e = ex2f(fmaf(a, C1F, -C1F));
                    se_[r2] += e;
                    colse[idx] += e;
                    if ((pmr >> bp) & 1) sp_[r2] += a;
                    colsp[idx] += (labi == lbjv[idx]) ? a : 0.f;
                }
        }
    }

    // row merge: lanes xor 1,2 -> rowred[wn]
#pragma unroll
    for (int o = 1; o <= 2; o <<= 1)
#pragma unroll
        for (int r2 = 0; r2 < 4; r2++) {
            se_[r2] += __shfl_xor_sync(0xffffffffu, se_[r2], o);
            sp_[r2] += __shfl_xor_sync(0xffffffffu, sp_[r2], o);
        }
    if ((lane & 3) == 0) {
#pragma unroll
        for (int r2 = 0; r2 < 4; r2++) {
            int rowg = m0 + (r2 >> 1) * 16 + (lane >> 2) + (r2 & 1) * 8;
            rowred[(wn * 128 + rowg) * 2] = se_[r2];
            rowred[(wn * 128 + rowg) * 2 + 1] = sp_[r2];
        }
    }
    // col merge: lanes xor 4,8,16 -> colred[wm]
    if (!diag) {
#pragma unroll
        for (int idx = 0; idx < 8; idx++)
#pragma unroll
            for (int o = 4; o <= 16; o <<= 1) {
                colse[idx] += __shfl_xor_sync(0xffffffffu, colse[idx], o);
                colsp[idx] += __shfl_xor_sync(0xffffffffu, colsp[idx], o);
            }
        if ((lane >> 2) == 0) {
#pragma unroll
            for (int idx = 0; idx < 8; idx++) {
                int col = n0 + (idx >> 1) * 8 + sh + (idx & 1);
                colred[(wm * 128 + col) * 2] = colse[idx];
                colred[(wm * 128 + col) * 2 + 1] = colsp[idx];
            }
        }
    }
    __syncthreads();

    // global accumulation (256 (row,stat) pairs, 256 (col,stat) pairs)
    if (tid < 256) {
        int row = tid >> 1, st = tid & 1;
        float v = rowred[row * 2 + st] + rowred[(128 + row) * 2 + st] +
                  rowred[(256 + row) * 2 + st] + rowred[(384 + row) * 2 + st];
        atomicAdd((st ? g_sp : g_se) + b * LL + i0 + row, v);
    } else if (!diag) {
        int u = tid - 256;
        int col = u >> 1, st = u & 1;
        float v = colred[col * 2 + st] + colred[(128 + col) * 2 + st] +
                  colred[(256 + col) * 2 + st] + colred[(384 + col) * 2 + st];
        atomicAdd((st ? g_sp : g_se) + b * LL + j0 + col, v);
    }
}

// ---------------------------------------------------------------------------
// Kernel 3: per-anchor loss + deterministic final scalar (last CTA).
// Grid 128 CTAs x 256 threads, one anchor per thread.
// ---------------------------------------------------------------------------
__global__ __launch_bounds__(256)
void kern_loss(const int* __restrict__ amask, const int* __restrict__ labels,
               float* __restrict__ out) {
    __shared__ float wp[8];
    __shared__ int lastf;
    const int tid = threadIdx.x, lane = tid & 31, wid = tid >> 5;
    const int b = blockIdx.x >> 2;
    const int a = b * LL + (blockIdx.x & 3) * 256 + tid;

    int lb = labels[a];
    int valid = (amask[a] != 0) && (lb != -100);
    float al = 0.f;
    if (valid) {
        int cv = g_cv[b];
        float sec = g_se[a] - (float)(LL - cv) * ex2f(-C1F);
        sec = fmaxf(sec, 0.f) + 1e-12f;
        float npf = (float)(g_cnt4[b * 4 + lb] - 1);
        al = (INVT * g_sp[a] - npf * (INVT + __logf(sec))) / (npf + 1e-12f);
    }
#pragma unroll
    for (int o = 16; o >= 1; o >>= 1) al += __shfl_xor_sync(0xffffffffu, al, o);
    if (lane == 0) wp[wid] = al;
    __syncthreads();
    if (tid == 0) {
        float s = 0.f;
#pragma unroll
        for (int w = 0; w < 8; w++) s += wp[w];
        g_partial[blockIdx.x] = s;
    }
    __threadfence();
    if (tid == 0) lastf = (atomicAdd(&g_done, 1) == 127);
    __syncthreads();
    if (lastf) {
        __threadfence();
        if (tid < 32) {
            float ps = 0.f;
#pragma unroll
            for (int k = 0; k < 4; k++) ps += __ldcg(&g_partial[tid * 4 + k]);
            int cm = __ldcg(&g_cm[tid]);
            int cv = __ldcg(&g_cv[tid]);
            int ok = (cm >= 2);
            float nvv = (float)(cv >= 1 ? cv : 1);
            float lossb = ok ? (-ps / nvv) : 0.f;
            int ns = ok;
#pragma unroll
            for (int o = 16; o >= 1; o >>= 1) {
                lossb += __shfl_xor_sync(0xffffffffu, lossb, o);
                ns += __shfl_xor_sync(0xffffffffu, ns, o);
            }
            if (tid == 0) {
                out[0] = lossb / (float)(ns > 0 ? ns : 1);
                g_done = 0;
            }
        }
    }
}

// ---------------------------------------------------------------------------
extern "C" void kernel_launch(void* const* d_in, const int* in_sizes, int n_in,
                              void* d_out, int out_size) {
    const float* hid = (const float*)d_in[0];
    const float* W = (const float*)d_in[1];
    const float* bias = (const float*)d_in[2];
    const int* amask = (const int*)d_in[3];
    const int* labels = (const int*)d_in[4];
    float* out = (float*)d_out;

    cudaFuncSetAttribute(kern_proj, cudaFuncAttributeMaxDynamicSharedMemorySize, PROJ_SMEM);
    cudaFuncSetAttribute(kern_sim, cudaFuncAttributeMaxDynamicSharedMemorySize, SIM_SMEM);

    kern_wt<<<75, 256>>>(W);                                           // 0
    kern_proj<<<NROWS / 128, 256, PROJ_SMEM>>>(hid, bias, amask, labels); // 1
    kern_sim<<<BB * 36, 512, SIM_SMEM>>>(amask, labels);               // 2
    kern_loss<<<128, 256>>>(amask, labels, out);                       // 3
}